// round 15
// baseline (speedup 1.0000x reference)
#include <cuda_runtime.h>
#include <cuda_fp16.h>
#include <cstdint>
#include <math.h>

#define B_DIM 4
#define S_DIM 2048
#define T_DIM 256
#define H_DIM 2048
#define NHEAD 16
#define HD_DIM 128

#define BK 16
#define STAGE_PITCH 68       // fp32 epilogue staging pitch

// fp16 2-term GEMM: 128x128 tile, BK=16, 6-stage ring, 2 chunks/barrier, 2 CTAs/SM
#define FT 4096
#define FSTG 12288
#define FNST 6
#define FSMEM 73728          // max(6*12288, 128*68*4)

// Fused attention (128 q-rows, occ 1 — R12 proven optimum)
#define AS_KH 4096
#define AS_KL 12288
#define AS_STG 24576
#define AS_VOFF 131072
#define AS_SMEM (AS_VOFF + 3*8192)   // 155648

// ---------------------------------------------------------------------------
// Persistent scratch
// ---------------------------------------------------------------------------
__device__ __half g_hs16[8192*2048];
__device__ __half g_at16h[1024*2048], g_at16l[1024*2048];
__device__ __half g_Wq16h[2048*2048], g_Wq16l[2048*2048];
__device__ __half g_Wk16h[2048*2048], g_Wk16l[2048*2048];
__device__ __half g_Wv16[2048*2048];
__device__ __half g_Wo16h[2048*2048], g_Wo16l[2048*2048];
__device__ __half g_Q16[8192*2048];
__device__ __half g_K16h[1024*2048], g_K16l[1024*2048];
__device__ __half g_Vt16h[64*128*256], g_Vt16l[64*128*256];
__device__ __half g_C16[8192*2048];
__device__ float  g_D[8192*2048];

// ---------------------------------------------------------------------------
// Helpers
// ---------------------------------------------------------------------------
__device__ __forceinline__ uint32_t smem_to_u32(const void* p) {
    uint32_t a;
    asm("{ .reg .u64 t; cvta.to.shared.u64 t, %1; cvt.u32.u64 %0, t; }" : "=r"(a) : "l"(p));
    return a;
}
__device__ __forceinline__ void cp16(uint32_t dst, const void* src) {
    asm volatile("cp.async.cg.shared.global [%0], [%1], 16;" :: "r"(dst), "l"(src));
}
#define CP_COMMIT() asm volatile("cp.async.commit_group;")
#define CP_WAIT1()  asm volatile("cp.async.wait_group 1;")
#define CP_WAIT2()  asm volatile("cp.async.wait_group 2;")

__device__ __forceinline__ void ldmx4(uint32_t* r, uint32_t addr) {
    asm volatile("ldmatrix.sync.aligned.m8n8.x4.shared.b16 {%0,%1,%2,%3}, [%4];"
                 : "=r"(r[0]), "=r"(r[1]), "=r"(r[2]), "=r"(r[3]) : "r"(addr));
}
__device__ __forceinline__ void mma16816h(float* c, const uint32_t* a, const uint32_t* b) {
    asm volatile("mma.sync.aligned.m16n8k16.row.col.f32.f16.f16.f32 "
                 "{%0,%1,%2,%3}, {%4,%5,%6,%7}, {%8,%9}, {%0,%1,%2,%3};"
                 : "+f"(c[0]), "+f"(c[1]), "+f"(c[2]), "+f"(c[3])
                 : "r"(a[0]), "r"(a[1]), "r"(a[2]), "r"(a[3]), "r"(b[0]), "r"(b[1]));
}
__device__ __forceinline__ void split_pair_f16(float x0, float x1, uint32_t& hi, uint32_t& lo) {
    __half2 h = __floats2half2_rn(x0, x1);
    float r0 = x0 - __half2float(__low2half(h));
    float r1 = x1 - __half2float(__high2half(h));
    __half2 l = __floats2half2_rn(r0, r1);
    hi = *(uint32_t*)&h;
    lo = *(uint32_t*)&l;
}
__device__ __forceinline__ uint32_t pack_h2(float x0, float x1) {
    __half2 h = __floats2half2_rn(x0, x1);
    return *(uint32_t*)&h;
}
__device__ __forceinline__ uint32_t swz(int row, int seg) {
    return (row >> 7) * 4096 + (row & 127) * 32 + ((seg << 4) ^ ((row & 4) << 2));
}

// ---------------------------------------------------------------------------
// Pre-pass kernels
// ---------------------------------------------------------------------------
__global__ void split16_kernel(const float* __restrict__ in,
                               __half* __restrict__ hi, __half* __restrict__ lo)
{
    int idx = blockIdx.x * blockDim.x + threadIdx.x;
    float4 v = ((const float4*)in)[idx];
    uint32_t h0, l0, h1, l1;
    split_pair_f16(v.x, v.y, h0, l0);
    split_pair_f16(v.z, v.w, h1, l1);
    ((uint2*)hi)[idx] = make_uint2(h0, h1);
    ((uint2*)lo)[idx] = make_uint2(l0, l1);
}
// 3 weight splits in one launch (blockIdx.y selects tensor)
__global__ void split16x3_kernel(const float* __restrict__ in0, __half* __restrict__ h0, __half* __restrict__ l0,
                                 const float* __restrict__ in1, __half* __restrict__ h1, __half* __restrict__ l1,
                                 const float* __restrict__ in2, __half* __restrict__ h2, __half* __restrict__ l2)
{
    const int w = blockIdx.y;
    const float* in = (w == 0) ? in0 : (w == 1) ? in1 : in2;
    __half* hi = (w == 0) ? h0 : (w == 1) ? h1 : h2;
    __half* lo = (w == 0) ? l0 : (w == 1) ? l1 : l2;
    int idx = blockIdx.x * blockDim.x + threadIdx.x;
    float4 v = ((const float4*)in)[idx];
    uint32_t a0, b0, a1, b1;
    split_pair_f16(v.x, v.y, a0, b0);
    split_pair_f16(v.z, v.w, a1, b1);
    ((uint2*)hi)[idx] = make_uint2(a0, a1);
    ((uint2*)lo)[idx] = make_uint2(b0, b1);
}
__global__ void cast16_kernel(const float* __restrict__ in, __half* __restrict__ out)
{
    int idx = blockIdx.x * blockDim.x + threadIdx.x;
    float4 v = ((const float4*)in)[idx];
    ((uint2*)out)[idx] = make_uint2(pack_h2(v.x, v.y), pack_h2(v.z, v.w));
}

// ---------------------------------------------------------------------------
// fp16 2-term GEMM (Q/O proj): C = Ah*(Bh+Bl). 6-stage ring, 2 chunks/barrier.
//   MODE 0: +bias[col] -> fp16 single (Q-proj)
//   MODE 4: +bias[col] -> fp32 (O-proj)
// ---------------------------------------------------------------------------
template<int MODE>
__global__ void __launch_bounds__(256, 2)
mma_gemm_f16(const __half* __restrict__ Ah, const __half* __restrict__ Bh,
             const __half* __restrict__ Bl, const float* __restrict__ bias,
             float* __restrict__ Cf, __half* __restrict__ C1,
             int K, int lda, int ldb, int ldc)
{
    extern __shared__ __align__(16) char smem[];
    const int tid = threadIdx.x;
    const int wid = tid >> 5;
    const int lane = tid & 31;
    const int g = lane >> 2, ti = lane & 3;
    const int mwb = (wid >> 2) * 64;
    const int nwb = (wid & 3) * 32;
    const uint32_t sbase = smem_to_u32(smem);

    const int m0 = blockIdx.y * 128;
    const int n0 = blockIdx.x * 128;

    const int crow = tid >> 1;
    const int cseg = tid & 1;
    const size_t asrc = (size_t)(m0 + crow) * lda + cseg * 8;
    const size_t bsrc = (size_t)(n0 + crow) * ldb + cseg * 8;
    const uint32_t cdst = swz(crow, cseg);

    const int nchunk = K / BK;

    auto issue = [&](int c) {
        const uint32_t st = sbase + (c % FNST) * FSTG;
        const int kt = c * BK;
        cp16(st + cdst,          Ah + asrc + kt);
        cp16(st + cdst + FT,     Bh + bsrc + kt);
        cp16(st + cdst + 2*FT,   Bl + bsrc + kt);
    };

    float acc[4][4][4];
#pragma unroll
    for (int i = 0; i < 4; i++)
#pragma unroll
        for (int j = 0; j < 4; j++)
#pragma unroll
            for (int q = 0; q < 4; q++) acc[i][j][q] = 0.f;

    issue(0); CP_COMMIT();
    issue(1); CP_COMMIT();
    issue(2); CP_COMMIT();
    issue(3); CP_COMMIT();

    const int arow = lane & 15;
    const int aseg = lane >> 4;
    const int brow = (lane & 7) + ((lane >> 4) << 3);
    const int bseg = (lane >> 3) & 1;

    auto process = [&](int c) {
        const uint32_t sbuf = sbase + (c % FNST) * FSTG;
        uint32_t ah[4][4];
#pragma unroll
        for (int mf = 0; mf < 4; mf++)
            ldmx4(ah[mf], sbuf + swz(mwb + mf * 16 + arow, aseg));
#pragma unroll
        for (int np = 0; np < 2; np++) {
            uint32_t rh[4], rl[4];
            uint32_t bd = sbuf + FT + swz(nwb + np * 16 + brow, bseg);
            ldmx4(rh, bd);
            ldmx4(rl, bd + FT);
#pragma unroll
            for (int mf = 0; mf < 4; mf++) {
                mma16816h(acc[mf][2*np],   ah[mf], rh);
                mma16816h(acc[mf][2*np+1], ah[mf], rh + 2);
                mma16816h(acc[mf][2*np],   ah[mf], rl);
                mma16816h(acc[mf][2*np+1], ah[mf], rl + 2);
            }
        }
    };

    for (int c = 0; c < nchunk; c += 2) {
        CP_WAIT2();                // groups c, c+1 complete (always-commit keeps count exact)
        __syncthreads();           // all warps done with stages (c+4)%6, (c+5)%6 targets
        if (c + 4 < nchunk) issue(c + 4);
        CP_COMMIT();
        if (c + 5 < nchunk) issue(c + 5);
        CP_COMMIT();
        process(c);
        process(c + 1);
    }
    __syncthreads();

    float* stage = (float*)smem;
#pragma unroll
    for (int p = 0; p < 2; p++) {
        if (p) __syncthreads();
#pragma unroll
        for (int mf = 0; mf < 4; mf++)
#pragma unroll
            for (int e = 0; e < 2; e++) {
                const int nf = 2 * p + e;
                const int row = mwb + mf * 16 + g;
                const int cm = (wid & 3) * 16 + e * 8 + ti * 2;
                *(float2*)&stage[row * STAGE_PITCH + cm] =
                    make_float2(acc[mf][nf][0], acc[mf][nf][1]);
                *(float2*)&stage[(row + 8) * STAGE_PITCH + cm] =
                    make_float2(acc[mf][nf][2], acc[mf][nf][3]);
            }
        __syncthreads();
#pragma unroll
        for (int it = 0; it < 8; it++) {
            const int lin = it * 1024 + tid * 4;
            const int row = lin >> 6;
            const int cm = lin & 63;
            const int col = ((cm >> 4) << 5) + (p << 4) + (cm & 15);
            float4 v = *(float4*)&stage[row * STAGE_PITCH + cm];
            float4 b4 = *(const float4*)(bias + n0 + col);
            if (MODE == 0) {
                size_t off = (size_t)(m0 + row) * ldc + n0 + col;
                *(uint2*)(C1 + off) = make_uint2(pack_h2(v.x + b4.x, v.y + b4.y),
                                                 pack_h2(v.z + b4.z, v.w + b4.w));
            } else {
                float4 o = make_float4(v.x + b4.x, v.y + b4.y, v.z + b4.z, v.w + b4.w);
                *(float4*)(Cf + (size_t)(m0 + row) * ldc + n0 + col) = o;
            }
        }
    }
}

// ---------------------------------------------------------------------------
// Combined K-proj + V-proj in one launch (z=0: K-proj, z=1: V-proj).
// K-proj: C = at16h*(Wk16h+Wk16l) + bk[col] -> K16h/l pair  (M=1024, N=2048)
// V-proj: C = Wv16*(at16h+at16l)  + bv[row] -> Vt scatter    (M=2048, N=1024)
// 6-stage ring, 2 chunks/barrier, 2 CTAs/SM.
// ---------------------------------------------------------------------------
__global__ void __launch_bounds__(256, 2)
mma_gemm_kv(const __half* __restrict__ at16h, const __half* __restrict__ at16l,
            const __half* __restrict__ Wk16h, const __half* __restrict__ Wk16l,
            const __half* __restrict__ Wv16,
            const float* __restrict__ bk, const float* __restrict__ bv,
            __half* __restrict__ K16h, __half* __restrict__ K16l,
            __half* __restrict__ Vth, __half* __restrict__ Vtl)
{
    extern __shared__ __align__(16) char smem[];
    const int kv = blockIdx.z;    // 0 = K-proj, 1 = V-proj
    if ((kv == 0 && blockIdx.y >= 8) || (kv == 1 && blockIdx.x >= 8)) return;

    const __half* Ah = kv ? Wv16  : at16h;
    const __half* Bh = kv ? at16h : Wk16h;
    const __half* Bl = kv ? at16l : Wk16l;
    const float* bias = kv ? bv : bk;

    const int tid = threadIdx.x;
    const int wid = tid >> 5;
    const int lane = tid & 31;
    const int g = lane >> 2, ti = lane & 3;
    const int mwb = (wid >> 2) * 64;
    const int nwb = (wid & 3) * 32;
    const uint32_t sbase = smem_to_u32(smem);

    const int m0 = blockIdx.y * 128;
    const int n0 = blockIdx.x * 128;

    const int crow = tid >> 1;
    const int cseg = tid & 1;
    const size_t asrc = (size_t)(m0 + crow) * H_DIM + cseg * 8;
    const size_t bsrc = (size_t)(n0 + crow) * H_DIM + cseg * 8;
    const uint32_t cdst = swz(crow, cseg);

    const int nchunk = H_DIM / BK;   // 128

    auto issue = [&](int c) {
        const uint32_t st = sbase + (c % FNST) * FSTG;
        const int kt = c * BK;
        cp16(st + cdst,          Ah + asrc + kt);
        cp16(st + cdst + FT,     Bh + bsrc + kt);
        cp16(st + cdst + 2*FT,   Bl + bsrc + kt);
    };

    float acc[4][4][4];
#pragma unroll
    for (int i = 0; i < 4; i++)
#pragma unroll
        for (int j = 0; j < 4; j++)
#pragma unroll
            for (int q = 0; q < 4; q++) acc[i][j][q] = 0.f;

    issue(0); CP_COMMIT();
    issue(1); CP_COMMIT();
    issue(2); CP_COMMIT();
    issue(3); CP_COMMIT();

    const int arow = lane & 15;
    const int aseg = lane >> 4;
    const int brow = (lane & 7) + ((lane >> 4) << 3);
    const int bseg = (lane >> 3) & 1;

    auto process = [&](int c) {
        const uint32_t sbuf = sbase + (c % FNST) * FSTG;
        uint32_t ah[4][4];
#pragma unroll
        for (int mf = 0; mf < 4; mf++)
            ldmx4(ah[mf], sbuf + swz(mwb + mf * 16 + arow, aseg));
#pragma unroll
        for (int np = 0; np < 2; np++) {
            uint32_t rh[4], rl[4];
            uint32_t bd = sbuf + FT + swz(nwb + np * 16 + brow, bseg);
            ldmx4(rh, bd);
            ldmx4(rl, bd + FT);
#pragma unroll
            for (int mf = 0; mf < 4; mf++) {
                mma16816h(acc[mf][2*np],   ah[mf], rh);
                mma16816h(acc[mf][2*np+1], ah[mf], rh + 2);
                mma16816h(acc[mf][2*np],   ah[mf], rl);
                mma16816h(acc[mf][2*np+1], ah[mf], rl + 2);
            }
        }
    };

    for (int c = 0; c < nchunk; c += 2) {
        CP_WAIT2();
        __syncthreads();
        if (c + 4 < nchunk) issue(c + 4);
        CP_COMMIT();
        if (c + 5 < nchunk) issue(c + 5);
        CP_COMMIT();
        process(c);
        process(c + 1);
    }
    __syncthreads();

    float* stage = (float*)smem;
#pragma unroll
    for (int p = 0; p < 2; p++) {
        if (p) __syncthreads();
#pragma unroll
        for (int mf = 0; mf < 4; mf++)
#pragma unroll
            for (int e = 0; e < 2; e++) {
                const int nf = 2 * p + e;
                const int row = mwb + mf * 16 + g;
                const int cm = (wid & 3) * 16 + e * 8 + ti * 2;
                *(float2*)&stage[row * STAGE_PITCH + cm] =
                    make_float2(acc[mf][nf][0], acc[mf][nf][1]);
                *(float2*)&stage[(row + 8) * STAGE_PITCH + cm] =
                    make_float2(acc[mf][nf][2], acc[mf][nf][3]);
            }
        __syncthreads();
#pragma unroll
        for (int it = 0; it < 8; it++) {
            const int lin = it * 1024 + tid * 4;
            const int row = lin >> 6;
            const int cm = lin & 63;
            const int col = ((cm >> 4) << 5) + (p << 4) + (cm & 15);
            float4 v = *(float4*)&stage[row * STAGE_PITCH + cm];
            if (kv == 0) {          // K-proj epilogue (bias per col, hi/lo pair)
                float4 b4 = *(const float4*)(bias + n0 + col);
                size_t off = (size_t)(m0 + row) * H_DIM + n0 + col;
                uint32_t h0, l0, h1, l1;
                split_pair_f16(v.x + b4.x, v.y + b4.y, h0, l0);
                split_pair_f16(v.z + b4.z, v.w + b4.w, h1, l1);
                *(uint2*)(K16h + off) = make_uint2(h0, h1);
                *(uint2*)(K16l + off) = make_uint2(l0, l1);
            } else {                // V-proj scatter (bias per row)
                const int gr = m0 + row;             // feature = h*128+d
                const int h = gr >> 7, d = gr & 127;
                const int n = n0 + col;              // b*256+t
                const int b = n >> 8, t = n & 255;
                const float br = bias[gr];
                size_t off = ((size_t)(b * NHEAD + h) * HD_DIM + d) * T_DIM + t;
                uint32_t h0, l0, h1, l1;
                split_pair_f16(v.x + br, v.y + br, h0, l0);
                split_pair_f16(v.z + br, v.w + br, h1, l1);
                *(uint2*)(Vth + off) = make_uint2(h0, h1);
                *(uint2*)(Vtl + off) = make_uint2(l0, l1);
            }
        }
    }
}

// ---------------------------------------------------------------------------
// Fused attention (R12 optimum): 128 q-rows per CTA, occ 1, all fp16 2-term.
// ---------------------------------------------------------------------------
__global__ void __launch_bounds__(256, 1)
fused_attn_kernel(const __half* __restrict__ Q16,
                  const __half* __restrict__ K16h, const __half* __restrict__ K16l,
                  const __half* __restrict__ V16h, const __half* __restrict__ V16l,
                  const int* __restrict__ mask, __half* __restrict__ C16)
{
    extern __shared__ __align__(16) char dsm[];
    __shared__ float red[128][4];
    __shared__ int smask[T_DIM];

    const int tid = threadIdx.x;
    const int wid = tid >> 5;
    const int lane = tid & 31;
    const int g = lane >> 2, ti = lane & 3;
    const int mwb = (wid >> 2) * 64;
    const int nwb = (wid & 3) * 64;
    const uint32_t sbase = smem_to_u32(dsm);

    const int m0 = blockIdx.y * 128;
    const int z = blockIdx.z;
    const int bb = z >> 4, hh = z & 15;
    const __half* pQ  = Q16  + (size_t)bb * S_DIM * H_DIM + hh * HD_DIM;
    const __half* pKh = K16h + (size_t)bb * T_DIM * H_DIM + hh * HD_DIM;
    const __half* pKl = K16l + (size_t)bb * T_DIM * H_DIM + hh * HD_DIM;

    smask[tid] = mask[bb * T_DIM + tid];

    const int crow = tid >> 1, cseg = tid & 1;
    const size_t qsrc  = (size_t)(m0 + crow) * H_DIM + cseg * 8;
    const size_t ksrc0 = (size_t)crow * H_DIM + cseg * 8;
    const size_t ksrc1 = (size_t)(crow + 128) * H_DIM + cseg * 8;
    const uint32_t adst = swz(crow, cseg);
    const uint32_t bdst0 = swz(crow, cseg);
    const uint32_t bdst1 = swz(crow + 128, cseg);

    auto issue = [&](int c) {
        const uint32_t st = sbase + (c % 3) * AS_STG;
        const int kt = c * BK;
        cp16(st + adst,            pQ  + qsrc + kt);
        cp16(st + AS_KH + bdst0,   pKh + ksrc0 + kt);
        cp16(st + AS_KH + bdst1,   pKh + ksrc1 + kt);
        cp16(st + AS_KL + bdst0,   pKl + ksrc0 + kt);
        cp16(st + AS_KL + bdst1,   pKl + ksrc1 + kt);
    };

    float acc[4][8][4];
#pragma unroll
    for (int i = 0; i < 4; i++)
#pragma unroll
        for (int j = 0; j < 8; j++)
#pragma unroll
            for (int q = 0; q < 4; q++) acc[i][j][q] = 0.f;

    issue(0); CP_COMMIT();
    issue(1); CP_COMMIT();

    const int arow = lane & 15;
    const int aseg = lane >> 4;
    const int brow = (lane & 7) + ((lane >> 4) << 3);
    const int bseg = (lane >> 3) & 1;

    for (int c = 0; c < 8; c++) {          // K = HD = 128
        CP_WAIT1();
        __syncthreads();
        if (c + 2 < 8) issue(c + 2);
        CP_COMMIT();

        const uint32_t sbuf = sbase + (c % 3) * AS_STG;
        uint32_t ah[4][4];
#pragma unroll
        for (int mf = 0; mf < 4; mf++)
            ldmx4(ah[mf], sbuf + swz(mwb + mf * 16 + arow, aseg));
#pragma unroll
        for (int np = 0; np < 4; np++) {
            uint32_t rh[4], rl[4];
            uint32_t bd = sbuf + AS_KH + swz(nwb + np * 16 + brow, bseg);
            ldmx4(rh, bd);
            ldmx4(rl, bd + (AS_KL - AS_KH));
#pragma unroll
            for (int mf = 0; mf < 4; mf++) {
                mma16816h(acc[mf][2*np],   ah[mf], rh);
                mma16816h(acc[mf][2*np+1], ah[mf], rh + 2);
                mma16816h(acc[mf][2*np],   ah[mf], rl);
                mma16816h(acc[mf][2*np+1], ah[mf], rl + 2);
            }
        }
    }

    // Prefetch first V tiles (region does not overlap scores stages)
    const __half* pVh = V16h + (size_t)z * HD_DIM * T_DIM;
    const __half* pVl = V16l + (size_t)z * HD_DIM * T_DIM;
    const size_t vsrc = (size_t)crow * T_DIM + cseg * 8;
    const uint32_t vdst = swz(crow, cseg);
    auto issueV = [&](int c) {
        const uint32_t st = sbase + AS_VOFF + (c % 3) * 8192;
        cp16(st + vdst,        pVh + vsrc + c * 16);
        cp16(st + vdst + 4096, pVl + vsrc + c * 16);
    };
    issueV(0); CP_COMMIT();
    issueV(1); CP_COMMIT();
    __syncthreads();   // all warps done with scores stages before P overwrite

    // ---- mask/scale/clip + per-row softmax ----
    const float invs = 0.08838834764831845f;   // 1/sqrt(128)
    float rmax[4][2], rsum[4][2];
#pragma unroll
    for (int mf = 0; mf < 4; mf++) {
        float mx0 = -1e30f, mx1 = -1e30f;
#pragma unroll
        for (int nf = 0; nf < 8; nf++) {
            const int col = nwb + nf * 8 + ti * 2;
            const bool k0 = smask[col] != 0;
            const bool k1 = smask[col + 1] != 0;
            float* a = acc[mf][nf];
            a[0] = k0 ? fminf(fmaxf(a[0] * invs, -50.f), 50.f) : -50.f;
            a[1] = k1 ? fminf(fmaxf(a[1] * invs, -50.f), 50.f) : -50.f;
            a[2] = k0 ? fminf(fmaxf(a[2] * invs, -50.f), 50.f) : -50.f;
            a[3] = k1 ? fminf(fmaxf(a[3] * invs, -50.f), 50.f) : -50.f;
            mx0 = fmaxf(mx0, fmaxf(a[0], a[1]));
            mx1 = fmaxf(mx1, fmaxf(a[2], a[3]));
        }
        mx0 = fmaxf(mx0, __shfl_xor_sync(0xffffffffu, mx0, 1));
        mx0 = fmaxf(mx0, __shfl_xor_sync(0xffffffffu, mx0, 2));
        mx1 = fmaxf(mx1, __shfl_xor_sync(0xffffffffu, mx1, 1));
        mx1 = fmaxf(mx1, __shfl_xor_sync(0xffffffffu, mx1, 2));
        if (ti == 0) {
            red[mwb + mf * 16 + g][wid & 3]     = mx0;
            red[mwb + mf * 16 + g + 8][wid & 3] = mx1;
        }
    }
    __syncthreads();
#pragma unroll
    for (int mf = 0; mf < 4; mf++) {
        float4 r0 = *(float4*)red[mwb + mf * 16 + g];
        rmax[mf][0] = fmaxf(fmaxf(r0.x, r0.y), fmaxf(r0.z, r0.w));
        float4 r1 = *(float4*)red[mwb + mf * 16 + g + 8];
        rmax[mf][1] = fmaxf(fmaxf(r1.x, r1.y), fmaxf(r1.z, r1.w));
    }
    __syncthreads();
#pragma unroll
    for (int mf = 0; mf < 4; mf++) {
        float s0 = 0.f, s1 = 0.f;
#pragma unroll
        for (int nf = 0; nf < 8; nf++) {
            float* a = acc[mf][nf];
            a[0] = __expf(a[0] - rmax[mf][0]); s0 += a[0];
            a[1] = __expf(a[1] - rmax[mf][0]); s0 += a[1];
            a[2] = __expf(a[2] - rmax[mf][1]); s1 += a[2];
            a[3] = __expf(a[3] - rmax[mf][1]); s1 += a[3];
        }
        s0 += __shfl_xor_sync(0xffffffffu, s0, 1);
        s0 += __shfl_xor_sync(0xffffffffu, s0, 2);
        s1 += __shfl_xor_sync(0xffffffffu, s1, 1);
        s1 += __shfl_xor_sync(0xffffffffu, s1, 2);
        if (ti == 0) {
            red[mwb + mf * 16 + g][wid & 3]     = s0;
            red[mwb + mf * 16 + g + 8][wid & 3] = s1;
        }
    }
    __syncthreads();
#pragma unroll
    for (int mf = 0; mf < 4; mf++) {
        float4 r0 = *(float4*)red[mwb + mf * 16 + g];
        rsum[mf][0] = 1.f / (r0.x + r0.y + r0.z + r0.w);
        float4 r1 = *(float4*)red[mwb + mf * 16 + g + 8];
        rsum[mf][1] = 1.f / (r1.x + r1.y + r1.z + r1.w);
    }

    // ---- stage P (single fp16) into SMEM A-operand tiles: chunk ch at ch*4096 ----
#pragma unroll
    for (int mf = 0; mf < 4; mf++) {
        const int r0 = mwb + mf * 16 + g;
#pragma unroll
        for (int nf = 0; nf < 8; nf++) {
            const int col = nwb + nf * 8 + ti * 2;
            const int ch = col >> 4;
            const int colc = col & 15;
            const uint32_t cb = ch * 4096 + (((colc >> 3) << 4) ^ ((r0 & 4) << 2))
                              + (colc & 7) * 2 + r0 * 32;
            float* a = acc[mf][nf];
            *(uint32_t*)(dsm + cb)       = pack_h2(a[0] * rsum[mf][0], a[1] * rsum[mf][0]);
            *(uint32_t*)(dsm + cb + 256) = pack_h2(a[2] * rsum[mf][1], a[3] * rsum[mf][1]);
        }
    }
    __syncthreads();

    // ---- PV mainloop: ctx[128 s][128 d], K = T = 256, 16 chunks ----
    float ctx[4][4][4];
#pragma unroll
    for (int i = 0; i < 4; i++)
#pragma unroll
        for (int j = 0; j < 4; j++)
#pragma unroll
            for (int q = 0; q < 4; q++) ctx[i][j][q] = 0.f;

    const int nwb2 = (wid & 3) * 32;
    for (int c = 0; c < 16; c++) {
        CP_WAIT1();
        __syncthreads();
        if (c + 2 < 16) issueV(c + 2);
        CP_COMMIT();

        const uint32_t pbuf = sbase + c * 4096;
        const uint32_t vbuf = sbase + AS_VOFF + (c % 3) * 8192;
        uint32_t ah[4][4];
#pragma unroll
        for (int mf = 0; mf < 4; mf++)
            ldmx4(ah[mf], pbuf + swz(mwb + mf * 16 + arow, aseg));
#pragma unroll
        for (int np = 0; np < 2; np++) {
            uint32_t rh[4], rl[4];
            uint32_t bd = vbuf + swz(nwb2 + np * 16 + brow, bseg);
            ldmx4(rh, bd);
            ldmx4(rl, bd + 4096);
#pragma unroll
            for (int mf = 0; mf < 4; mf++) {
                mma16816h(ctx[mf][2*np],   ah[mf], rh);
                mma16816h(ctx[mf][2*np+1], ah[mf], rh + 2);
                mma16816h(ctx[mf][2*np],   ah[mf], rl);
                mma16816h(ctx[mf][2*np+1], ah[mf], rl + 2);
            }
        }
    }
    __syncthreads();

    // ---- ctx scatter -> single fp16 [b*S+s, h*128+d] ----
    float* stage = (float*)dsm;
#pragma unroll
    for (int p = 0; p < 2; p++) {
        if (p) __syncthreads();
#pragma unroll
        for (int mf = 0; mf < 4; mf++)
#pragma unroll
            for (int e = 0; e < 2; e++) {
                const int nf = 2 * p + e;
                const int row = mwb + mf * 16 + g;
                const int cm = (wid & 3) * 16 + e * 8 + ti * 2;
                *(float2*)&stage[row * STAGE_PITCH + cm] =
                    make_float2(ctx[mf][nf][0], ctx[mf][nf][1]);
                *(float2*)&stage[(row + 8) * STAGE_PITCH + cm] =
                    make_float2(ctx[mf][nf][2], ctx[mf][nf][3]);
            }
        __syncthreads();
#pragma unroll
        for (int it = 0; it < 8; it++) {
            const int lin = it * 1024 + tid * 4;
            const int row = lin >> 6;
            const int cm = lin & 63;
            const int col = ((cm >> 4) << 5) + (p << 4) + (cm & 15);
            float4 v = *(float4*)&stage[row * STAGE_PITCH + cm];
            size_t off = (size_t)(bb * S_DIM + m0 + row) * H_DIM + hh * HD_DIM + col;
            *(uint2*)(C16 + off) = make_uint2(pack_h2(v.x, v.y), pack_h2(v.z, v.w));
        }
    }
}

// ---------------------------------------------------------------------------
// LayerNorm
// ---------------------------------------------------------------------------
__device__ __forceinline__ float block_sum(float v)
{
    __shared__ float red[8];
#pragma unroll
    for (int o = 16; o; o >>= 1) v += __shfl_xor_sync(0xffffffffu, v, o);
    int w = threadIdx.x >> 5;
    if ((threadIdx.x & 31) == 0) red[w] = v;
    __syncthreads();
    float t = (threadIdx.x < 8) ? red[threadIdx.x] : 0.f;
    if (threadIdx.x < 32) {
#pragma unroll
        for (int o = 4; o; o >>= 1) t += __shfl_xor_sync(0xffffffffu, t, o);
        if (threadIdx.x == 0) red[0] = t;
    }
    __syncthreads();
    float r = red[0];
    __syncthreads();
    return r;
}

__global__ void ln_kernel(const float* __restrict__ D, const float* __restrict__ gamma,
                          const float* __restrict__ beta, const float* __restrict__ rsp,
                          float* __restrict__ out)
{
    int row = blockIdx.x;
    int tid = threadIdx.x;
    float rs = fminf(fmaxf(rsp[0], 0.f), 0.3f);

    const float* d = D + (size_t)row * H_DIM;
    float4 u0 = *(const float4*)(d + tid * 4);
    float4 u1 = *(const float4*)(d + 1024 + tid * 4);
    float x[8] = {rs*u0.x, rs*u0.y, rs*u0.z, rs*u0.w,
                  rs*u1.x, rs*u1.y, rs*u1.z, rs*u1.w};

    float ps = 0.f;
#pragma unroll
    for (int i = 0; i < 8; i++) ps += x[i];
    float mean = block_sum(ps) * (1.f / 2048.f);

    float pv = 0.f;
#pragma unroll
    for (int i = 0; i < 8; i++) { float dd = x[i] - mean; pv += dd * dd; }
    float var = block_sum(pv) * (1.f / 2048.f);
    float inv = rsqrtf(var + 1e-5f);

    float4 gz0 = *(const float4*)(gamma + tid * 4);
    float4 gz1 = *(const float4*)(gamma + 1024 + tid * 4);
    float4 bz0 = *(const float4*)(beta + tid * 4);
    float4 bz1 = *(const float4*)(beta + 1024 + tid * 4);

    float* o = out + (size_t)row * H_DIM;
    *(float4*)(o + tid * 4) = make_float4(
        (x[0]-mean)*inv*gz0.x + bz0.x, (x[1]-mean)*inv*gz0.y + bz0.y,
        (x[2]-mean)*inv*gz0.z + bz0.z, (x[3]-mean)*inv*gz0.w + bz0.w);
    *(float4*)(o + 1024 + tid * 4) = make_float4(
        (x[4]-mean)*inv*gz1.x + bz1.x, (x[5]-mean)*inv*gz1.y + bz1.y,
        (x[6]-mean)*inv*gz1.z + bz1.z, (x[7]-mean)*inv*gz1.w + bz1.w);
}

// ---------------------------------------------------------------------------
// Launch
// ---------------------------------------------------------------------------
extern "C" void kernel_launch(void* const* d_in, const int* in_sizes, int n_in,
                              void* d_out, int out_size)
{
    const float* hs    = (const float*)d_in[0];
    const float* at    = (const float*)d_in[1];
    const int*   mask  = (const int*)  d_in[2];
    const float* Wq    = (const float*)d_in[3];
    const float* bq    = (const float*)d_in[4];
    const float* Wk    = (const float*)d_in[5];
    const float* bk    = (const float*)d_in[6];
    const float* Wv    = (const float*)d_in[7];
    const float* bv    = (const float*)d_in[8];
    const float* Wo    = (const float*)d_in[9];
    const float* bo    = (const float*)d_in[10];
    const float* gamma = (const float*)d_in[11];
    const float* beta  = (const float*)d_in[12];
    const float* rsp   = (const float*)d_in[13];
    float* out = (float*)d_out;

    __half *hs16, *at16h, *at16l, *Wq16h, *Wq16l, *Wk16h, *Wk16l, *Wv16, *Wo16h, *Wo16l;
    __half *Q16, *K16h, *K16l, *Vt16h, *Vt16l, *C16;
    float *Db;
    cudaGetSymbolAddress((void**)&hs16,  g_hs16);
    cudaGetSymbolAddress((void**)&at16h, g_at16h); cudaGetSymbolAddress((void**)&at16l, g_at16l);
    cudaGetSymbolAddress((void**)&Wq16h, g_Wq16h); cudaGetSymbolAddress((void**)&Wq16l, g_Wq16l);
    cudaGetSymbolAddress((void**)&Wk16h, g_Wk16h); cudaGetSymbolAddress((void**)&Wk16l, g_Wk16l);
    cudaGetSymbolAddress((void**)&Wv16,  g_Wv16);
    cudaGetSymbolAddress((void**)&Wo16h, g_Wo16h); cudaGetSymbolAddress((void**)&Wo16l, g_Wo16l);
    cudaGetSymbolAddress((void**)&Q16,   g_Q16);
    cudaGetSymbolAddress((void**)&K16h,  g_K16h);  cudaGetSymbolAddress((void**)&K16l,  g_K16l);
    cudaGetSymbolAddress((void**)&Vt16h, g_Vt16h); cudaGetSymbolAddress((void**)&Vt16l, g_Vt16l);
    cudaGetSymbolAddress((void**)&C16,   g_C16);
    cudaGetSymbolAddress((void**)&Db,    g_D);

    cudaFuncSetAttribute(mma_gemm_f16<0>, cudaFuncAttributeMaxDynamicSharedMemorySize, FSMEM);
    cudaFuncSetAttribute(mma_gemm_f16<4>, cudaFuncAttributeMaxDynamicSharedMemorySize, FSMEM);
    cudaFuncSetAttribute(mma_gemm_kv,     cudaFuncAttributeMaxDynamicSharedMemorySize, FSMEM);
    cudaFuncSetAttribute(fused_attn_kernel, cudaFuncAttributeMaxDynamicSharedMemorySize, AS_SMEM);

    // Pre-pass (4 launches)
    cast16_kernel<<<16384, 256>>>(hs, hs16);
    cast16_kernel<<<4096, 256>>>(Wv, Wv16);
    split16_kernel<<<2048, 256>>>(at, at16h, at16l);
    split16x3_kernel<<<dim3(4096, 3), 256>>>(Wq, Wq16h, Wq16l,
                                             Wk, Wk16h, Wk16l,
                                             Wo, Wo16h, Wo16l);

    // Q projection -> fp16 single
    mma_gemm_f16<0><<<dim3(16, 64), 256, FSMEM>>>(hs16, Wq16h, Wq16l, bq,
                                                  nullptr, Q16, 2048, 2048, 2048, 2048);
    // K-proj + V-proj in one launch (concurrent chip fill)
    mma_gemm_kv<<<dim3(16, 16, 2), 256, FSMEM>>>(at16h, at16l, Wk16h, Wk16l, Wv16,
                                                 bk, bv, K16h, K16l, Vt16h, Vt16l);
    // Fused scores + softmax + PV -> ctx fp16
    fused_attn_kernel<<<dim3(1, 16, 64), 256, AS_SMEM>>>(Q16, K16h, K16l,
                                                         Vt16h, Vt16l, mask, C16);
    // O projection -> fp32
    mma_gemm_f16<4><<<dim3(16, 64), 256, FSMEM>>>(C16, Wo16h, Wo16l, bo,
                                                  Db, nullptr, 2048, 2048, 2048, 2048);
    // residual scale + LayerNorm
    ln_kernel<<<8192, 256>>>(Db, gamma, beta, rsp, out);
}

// round 16
// speedup vs baseline: 1.0606x; 1.0606x over previous
#include <cuda_runtime.h>
#include <cuda_fp16.h>
#include <cstdint>
#include <math.h>

#define B_DIM 4
#define S_DIM 2048
#define T_DIM 256
#define H_DIM 2048
#define NHEAD 16
#define HD_DIM 128

#define BK 16
#define STAGE_PITCH 68       // fp32 epilogue staging pitch

// fp16 2-term GEMM: 128x128 tile, BK=16, 4-stage ring (12KB/stage), 2 CTAs/SM
#define FT 4096
#define FSTG 12288
#define SMEM_BYTES 49152

// Fused attention (128 q-rows, occ 1 — R12 proven optimum)
#define AS_KH 4096
#define AS_KL 12288
#define AS_STG 24576
#define AS_VOFF 131072
#define AS_SMEM (AS_VOFF + 3*8192)   // 155648

// ---------------------------------------------------------------------------
// Persistent scratch
// ---------------------------------------------------------------------------
__device__ __half g_hs16[8192*2048];
__device__ __half g_at16h[1024*2048], g_at16l[1024*2048];
__device__ __half g_Wq16h[2048*2048], g_Wq16l[2048*2048];
__device__ __half g_Wk16h[2048*2048], g_Wk16l[2048*2048];
__device__ __half g_Wv16[2048*2048];
__device__ __half g_Wo16h[2048*2048], g_Wo16l[2048*2048];
__device__ __half g_Q16[8192*2048];
__device__ __half g_K16h[1024*2048], g_K16l[1024*2048];
__device__ __half g_Vt16h[64*128*256], g_Vt16l[64*128*256];
__device__ __half g_C16[8192*2048];
__device__ float  g_D[8192*2048];

// ---------------------------------------------------------------------------
// Helpers
// ---------------------------------------------------------------------------
__device__ __forceinline__ uint32_t smem_to_u32(const void* p) {
    uint32_t a;
    asm("{ .reg .u64 t; cvta.to.shared.u64 t, %1; cvt.u32.u64 %0, t; }" : "=r"(a) : "l"(p));
    return a;
}
__device__ __forceinline__ void cp16(uint32_t dst, const void* src) {
    asm volatile("cp.async.cg.shared.global [%0], [%1], 16;" :: "r"(dst), "l"(src));
}
#define CP_COMMIT() asm volatile("cp.async.commit_group;")
#define CP_WAIT1()  asm volatile("cp.async.wait_group 1;")
#define CP_WAIT2()  asm volatile("cp.async.wait_group 2;")

__device__ __forceinline__ void ldmx4(uint32_t* r, uint32_t addr) {
    asm volatile("ldmatrix.sync.aligned.m8n8.x4.shared.b16 {%0,%1,%2,%3}, [%4];"
                 : "=r"(r[0]), "=r"(r[1]), "=r"(r[2]), "=r"(r[3]) : "r"(addr));
}
__device__ __forceinline__ void mma16816h(float* c, const uint32_t* a, const uint32_t* b) {
    asm volatile("mma.sync.aligned.m16n8k16.row.col.f32.f16.f16.f32 "
                 "{%0,%1,%2,%3}, {%4,%5,%6,%7}, {%8,%9}, {%0,%1,%2,%3};"
                 : "+f"(c[0]), "+f"(c[1]), "+f"(c[2]), "+f"(c[3])
                 : "r"(a[0]), "r"(a[1]), "r"(a[2]), "r"(a[3]), "r"(b[0]), "r"(b[1]));
}
__device__ __forceinline__ void split_pair_f16(float x0, float x1, uint32_t& hi, uint32_t& lo) {
    __half2 h = __floats2half2_rn(x0, x1);
    float r0 = x0 - __half2float(__low2half(h));
    float r1 = x1 - __half2float(__high2half(h));
    __half2 l = __floats2half2_rn(r0, r1);
    hi = *(uint32_t*)&h;
    lo = *(uint32_t*)&l;
}
__device__ __forceinline__ uint32_t pack_h2(float x0, float x1) {
    __half2 h = __floats2half2_rn(x0, x1);
    return *(uint32_t*)&h;
}
__device__ __forceinline__ uint32_t swz(int row, int seg) {
    return (row >> 7) * 4096 + (row & 127) * 32 + ((seg << 4) ^ ((row & 4) << 2));
}

// ---------------------------------------------------------------------------
// Pre-pass kernels
// ---------------------------------------------------------------------------
__global__ void split16_kernel(const float* __restrict__ in,
                               __half* __restrict__ hi, __half* __restrict__ lo)
{
    int idx = blockIdx.x * blockDim.x + threadIdx.x;
    float4 v = ((const float4*)in)[idx];
    uint32_t h0, l0, h1, l1;
    split_pair_f16(v.x, v.y, h0, l0);
    split_pair_f16(v.z, v.w, h1, l1);
    ((uint2*)hi)[idx] = make_uint2(h0, h1);
    ((uint2*)lo)[idx] = make_uint2(l0, l1);
}
// 3 weight splits in one launch (blockIdx.y selects tensor)
__global__ void split16x3_kernel(const float* __restrict__ in0, __half* __restrict__ h0, __half* __restrict__ l0,
                                 const float* __restrict__ in1, __half* __restrict__ h1, __half* __restrict__ l1,
                                 const float* __restrict__ in2, __half* __restrict__ h2, __half* __restrict__ l2)
{
    const int w = blockIdx.y;
    const float* in = (w == 0) ? in0 : (w == 1) ? in1 : in2;
    __half* hi = (w == 0) ? h0 : (w == 1) ? h1 : h2;
    __half* lo = (w == 0) ? l0 : (w == 1) ? l1 : l2;
    int idx = blockIdx.x * blockDim.x + threadIdx.x;
    float4 v = ((const float4*)in)[idx];
    uint32_t a0, b0, a1, b1;
    split_pair_f16(v.x, v.y, a0, b0);
    split_pair_f16(v.z, v.w, a1, b1);
    ((uint2*)hi)[idx] = make_uint2(a0, a1);
    ((uint2*)lo)[idx] = make_uint2(b0, b1);
}
__global__ void cast16_kernel(const float* __restrict__ in, __half* __restrict__ out)
{
    int idx = blockIdx.x * blockDim.x + threadIdx.x;
    float4 v = ((const float4*)in)[idx];
    ((uint2*)out)[idx] = make_uint2(pack_h2(v.x, v.y), pack_h2(v.z, v.w));
}

// ---------------------------------------------------------------------------
// fp16 2-term GEMM (R12 mainloop): C = Ah*(Bh+Bl). 4-stage ring, 2 CTAs/SM.
//   MODE 0: +bias[col] -> fp16 single (Q-proj)
//   MODE 4: +bias[col] -> fp32 (O-proj)
// ---------------------------------------------------------------------------
template<int MODE>
__global__ void __launch_bounds__(256, 2)
mma_gemm_f16(const __half* __restrict__ Ah, const __half* __restrict__ Bh,
             const __half* __restrict__ Bl, const float* __restrict__ bias,
             float* __restrict__ Cf, __half* __restrict__ C1,
             int K, int lda, int ldb, int ldc)
{
    __shared__ __align__(16) char smem[SMEM_BYTES];
    const int tid = threadIdx.x;
    const int wid = tid >> 5;
    const int lane = tid & 31;
    const int g = lane >> 2, ti = lane & 3;
    const int mwb = (wid >> 2) * 64;
    const int nwb = (wid & 3) * 32;
    const uint32_t sbase = smem_to_u32(smem);

    const int m0 = blockIdx.y * 128;
    const int n0 = blockIdx.x * 128;

    const int crow = tid >> 1;
    const int cseg = tid & 1;
    const size_t asrc = (size_t)(m0 + crow) * lda + cseg * 8;
    const size_t bsrc = (size_t)(n0 + crow) * ldb + cseg * 8;
    const uint32_t cdst = swz(crow, cseg);

    const int nchunk = K / BK;

    auto issue = [&](int c) {
        const uint32_t st = sbase + (c & 3) * FSTG;
        const int kt = c * BK;
        cp16(st + cdst,          Ah + asrc + kt);
        cp16(st + cdst + FT,     Bh + bsrc + kt);
        cp16(st + cdst + 2*FT,   Bl + bsrc + kt);
    };

    float acc[4][4][4];
#pragma unroll
    for (int i = 0; i < 4; i++)
#pragma unroll
        for (int j = 0; j < 4; j++)
#pragma unroll
            for (int q = 0; q < 4; q++) acc[i][j][q] = 0.f;

    issue(0); CP_COMMIT();
    issue(1); CP_COMMIT();
    issue(2); CP_COMMIT();

    const int arow = lane & 15;
    const int aseg = lane >> 4;
    const int brow = (lane & 7) + ((lane >> 4) << 3);
    const int bseg = (lane >> 3) & 1;

    for (int c = 0; c < nchunk; c++) {
        CP_WAIT2();
        __syncthreads();
        if (c + 3 < nchunk) issue(c + 3);
        CP_COMMIT();

        const uint32_t sbuf = sbase + (c & 3) * FSTG;
        uint32_t ah[4][4];
#pragma unroll
        for (int mf = 0; mf < 4; mf++)
            ldmx4(ah[mf], sbuf + swz(mwb + mf * 16 + arow, aseg));
#pragma unroll
        for (int np = 0; np < 2; np++) {
            uint32_t rh[4], rl[4];
            uint32_t bd = sbuf + FT + swz(nwb + np * 16 + brow, bseg);
            ldmx4(rh, bd);
            ldmx4(rl, bd + FT);
#pragma unroll
            for (int mf = 0; mf < 4; mf++) {
                mma16816h(acc[mf][2*np],   ah[mf], rh);
                mma16816h(acc[mf][2*np+1], ah[mf], rh + 2);
                mma16816h(acc[mf][2*np],   ah[mf], rl);
                mma16816h(acc[mf][2*np+1], ah[mf], rl + 2);
            }
        }
    }
    __syncthreads();

    float* stage = (float*)smem;
#pragma unroll
    for (int p = 0; p < 2; p++) {
        if (p) __syncthreads();
#pragma unroll
        for (int mf = 0; mf < 4; mf++)
#pragma unroll
            for (int e = 0; e < 2; e++) {
                const int nf = 2 * p + e;
                const int row = mwb + mf * 16 + g;
                const int cm = (wid & 3) * 16 + e * 8 + ti * 2;
                *(float2*)&stage[row * STAGE_PITCH + cm] =
                    make_float2(acc[mf][nf][0], acc[mf][nf][1]);
                *(float2*)&stage[(row + 8) * STAGE_PITCH + cm] =
                    make_float2(acc[mf][nf][2], acc[mf][nf][3]);
            }
        __syncthreads();
#pragma unroll
        for (int it = 0; it < 8; it++) {
            const int lin = it * 1024 + tid * 4;
            const int row = lin >> 6;
            const int cm = lin & 63;
            const int col = ((cm >> 4) << 5) + (p << 4) + (cm & 15);
            float4 v = *(float4*)&stage[row * STAGE_PITCH + cm];
            float4 b4 = *(const float4*)(bias + n0 + col);
            if (MODE == 0) {
                size_t off = (size_t)(m0 + row) * ldc + n0 + col;
                *(uint2*)(C1 + off) = make_uint2(pack_h2(v.x + b4.x, v.y + b4.y),
                                                 pack_h2(v.z + b4.z, v.w + b4.w));
            } else {
                float4 o = make_float4(v.x + b4.x, v.y + b4.y, v.z + b4.z, v.w + b4.w);
                *(float4*)(Cf + (size_t)(m0 + row) * ldc + n0 + col) = o;
            }
        }
    }
}

// ---------------------------------------------------------------------------
// Combined K-proj + V-proj in one launch (z=0: K-proj, z=1: V-proj).
// R12 mainloop (4-stage ring, static smem, occ 2).
// ---------------------------------------------------------------------------
__global__ void __launch_bounds__(256, 2)
mma_gemm_kv(const __half* __restrict__ at16h, const __half* __restrict__ at16l,
            const __half* __restrict__ Wk16h, const __half* __restrict__ Wk16l,
            const __half* __restrict__ Wv16,
            const float* __restrict__ bk, const float* __restrict__ bv,
            __half* __restrict__ K16h, __half* __restrict__ K16l,
            __half* __restrict__ Vth, __half* __restrict__ Vtl)
{
    __shared__ __align__(16) char smem[SMEM_BYTES];
    const int kv = blockIdx.z;    // 0 = K-proj, 1 = V-proj
    if ((kv == 0 && blockIdx.y >= 8) || (kv == 1 && blockIdx.x >= 8)) return;

    const __half* Ah = kv ? Wv16  : at16h;
    const __half* Bh = kv ? at16h : Wk16h;
    const __half* Bl = kv ? at16l : Wk16l;
    const float* bias = kv ? bv : bk;

    const int tid = threadIdx.x;
    const int wid = tid >> 5;
    const int lane = tid & 31;
    const int g = lane >> 2, ti = lane & 3;
    const int mwb = (wid >> 2) * 64;
    const int nwb = (wid & 3) * 32;
    const uint32_t sbase = smem_to_u32(smem);

    const int m0 = blockIdx.y * 128;
    const int n0 = blockIdx.x * 128;

    const int crow = tid >> 1;
    const int cseg = tid & 1;
    const size_t asrc = (size_t)(m0 + crow) * H_DIM + cseg * 8;
    const size_t bsrc = (size_t)(n0 + crow) * H_DIM + cseg * 8;
    const uint32_t cdst = swz(crow, cseg);

    const int nchunk = H_DIM / BK;   // 128

    auto issue = [&](int c) {
        const uint32_t st = sbase + (c & 3) * FSTG;
        const int kt = c * BK;
        cp16(st + cdst,          Ah + asrc + kt);
        cp16(st + cdst + FT,     Bh + bsrc + kt);
        cp16(st + cdst + 2*FT,   Bl + bsrc + kt);
    };

    float acc[4][4][4];
#pragma unroll
    for (int i = 0; i < 4; i++)
#pragma unroll
        for (int j = 0; j < 4; j++)
#pragma unroll
            for (int q = 0; q < 4; q++) acc[i][j][q] = 0.f;

    issue(0); CP_COMMIT();
    issue(1); CP_COMMIT();
    issue(2); CP_COMMIT();

    const int arow = lane & 15;
    const int aseg = lane >> 4;
    const int brow = (lane & 7) + ((lane >> 4) << 3);
    const int bseg = (lane >> 3) & 1;

    for (int c = 0; c < nchunk; c++) {
        CP_WAIT2();
        __syncthreads();
        if (c + 3 < nchunk) issue(c + 3);
        CP_COMMIT();

        const uint32_t sbuf = sbase + (c & 3) * FSTG;
        uint32_t ah[4][4];
#pragma unroll
        for (int mf = 0; mf < 4; mf++)
            ldmx4(ah[mf], sbuf + swz(mwb + mf * 16 + arow, aseg));
#pragma unroll
        for (int np = 0; np < 2; np++) {
            uint32_t rh[4], rl[4];
            uint32_t bd = sbuf + FT + swz(nwb + np * 16 + brow, bseg);
            ldmx4(rh, bd);
            ldmx4(rl, bd + FT);
#pragma unroll
            for (int mf = 0; mf < 4; mf++) {
                mma16816h(acc[mf][2*np],   ah[mf], rh);
                mma16816h(acc[mf][2*np+1], ah[mf], rh + 2);
                mma16816h(acc[mf][2*np],   ah[mf], rl);
                mma16816h(acc[mf][2*np+1], ah[mf], rl + 2);
            }
        }
    }
    __syncthreads();

    float* stage = (float*)smem;
#pragma unroll
    for (int p = 0; p < 2; p++) {
        if (p) __syncthreads();
#pragma unroll
        for (int mf = 0; mf < 4; mf++)
#pragma unroll
            for (int e = 0; e < 2; e++) {
                const int nf = 2 * p + e;
                const int row = mwb + mf * 16 + g;
                const int cm = (wid & 3) * 16 + e * 8 + ti * 2;
                *(float2*)&stage[row * STAGE_PITCH + cm] =
                    make_float2(acc[mf][nf][0], acc[mf][nf][1]);
                *(float2*)&stage[(row + 8) * STAGE_PITCH + cm] =
                    make_float2(acc[mf][nf][2], acc[mf][nf][3]);
            }
        __syncthreads();
#pragma unroll
        for (int it = 0; it < 8; it++) {
            const int lin = it * 1024 + tid * 4;
            const int row = lin >> 6;
            const int cm = lin & 63;
            const int col = ((cm >> 4) << 5) + (p << 4) + (cm & 15);
            float4 v = *(float4*)&stage[row * STAGE_PITCH + cm];
            if (kv == 0) {          // K-proj epilogue (bias per col, hi/lo pair)
                float4 b4 = *(const float4*)(bias + n0 + col);
                size_t off = (size_t)(m0 + row) * H_DIM + n0 + col;
                uint32_t h0, l0, h1, l1;
                split_pair_f16(v.x + b4.x, v.y + b4.y, h0, l0);
                split_pair_f16(v.z + b4.z, v.w + b4.w, h1, l1);
                *(uint2*)(K16h + off) = make_uint2(h0, h1);
                *(uint2*)(K16l + off) = make_uint2(l0, l1);
            } else {                // V-proj scatter (bias per row)
                const int gr = m0 + row;             // feature = h*128+d
                const int h = gr >> 7, d = gr & 127;
                const int n = n0 + col;              // b*256+t
                const int b = n >> 8, t = n & 255;
                const float br = bias[gr];
                size_t off = ((size_t)(b * NHEAD + h) * HD_DIM + d) * T_DIM + t;
                uint32_t h0, l0, h1, l1;
                split_pair_f16(v.x + br, v.y + br, h0, l0);
                split_pair_f16(v.z + br, v.w + br, h1, l1);
                *(uint2*)(Vth + off) = make_uint2(h0, h1);
                *(uint2*)(Vtl + off) = make_uint2(l0, l1);
            }
        }
    }
}

// ---------------------------------------------------------------------------
// Fused attention (R12 verbatim): 128 q-rows per CTA, occ 1, all fp16 2-term.
// ---------------------------------------------------------------------------
__global__ void __launch_bounds__(256, 1)
fused_attn_kernel(const __half* __restrict__ Q16,
                  const __half* __restrict__ K16h, const __half* __restrict__ K16l,
                  const __half* __restrict__ V16h, const __half* __restrict__ V16l,
                  const int* __restrict__ mask, __half* __restrict__ C16)
{
    extern __shared__ __align__(16) char dsm[];
    __shared__ float red[128][4];
    __shared__ int smask[T_DIM];

    const int tid = threadIdx.x;
    const int wid = tid >> 5;
    const int lane = tid & 31;
    const int g = lane >> 2, ti = lane & 3;
    const int mwb = (wid >> 2) * 64;
    const int nwb = (wid & 3) * 64;
    const uint32_t sbase = smem_to_u32(dsm);

    const int m0 = blockIdx.y * 128;
    const int z = blockIdx.z;
    const int bb = z >> 4, hh = z & 15;
    const __half* pQ  = Q16  + (size_t)bb * S_DIM * H_DIM + hh * HD_DIM;
    const __half* pKh = K16h + (size_t)bb * T_DIM * H_DIM + hh * HD_DIM;
    const __half* pKl = K16l + (size_t)bb * T_DIM * H_DIM + hh * HD_DIM;

    smask[tid] = mask[bb * T_DIM + tid];

    const int crow = tid >> 1, cseg = tid & 1;
    const size_t qsrc  = (size_t)(m0 + crow) * H_DIM + cseg * 8;
    const size_t ksrc0 = (size_t)crow * H_DIM + cseg * 8;
    const size_t ksrc1 = (size_t)(crow + 128) * H_DIM + cseg * 8;
    const uint32_t adst = swz(crow, cseg);
    const uint32_t bdst0 = swz(crow, cseg);
    const uint32_t bdst1 = swz(crow + 128, cseg);

    auto issue = [&](int c) {
        const uint32_t st = sbase + (c % 3) * AS_STG;
        const int kt = c * BK;
        cp16(st + adst,            pQ  + qsrc + kt);
        cp16(st + AS_KH + bdst0,   pKh + ksrc0 + kt);
        cp16(st + AS_KH + bdst1,   pKh + ksrc1 + kt);
        cp16(st + AS_KL + bdst0,   pKl + ksrc0 + kt);
        cp16(st + AS_KL + bdst1,   pKl + ksrc1 + kt);
    };

    float acc[4][8][4];
#pragma unroll
    for (int i = 0; i < 4; i++)
#pragma unroll
        for (int j = 0; j < 8; j++)
#pragma unroll
            for (int q = 0; q < 4; q++) acc[i][j][q] = 0.f;

    issue(0); CP_COMMIT();
    issue(1); CP_COMMIT();

    const int arow = lane & 15;
    const int aseg = lane >> 4;
    const int brow = (lane & 7) + ((lane >> 4) << 3);
    const int bseg = (lane >> 3) & 1;

    for (int c = 0; c < 8; c++) {          // K = HD = 128
        CP_WAIT1();
        __syncthreads();
        if (c + 2 < 8) issue(c + 2);
        CP_COMMIT();

        const uint32_t sbuf = sbase + (c % 3) * AS_STG;
        uint32_t ah[4][4];
#pragma unroll
        for (int mf = 0; mf < 4; mf++)
            ldmx4(ah[mf], sbuf + swz(mwb + mf * 16 + arow, aseg));
#pragma unroll
        for (int np = 0; np < 4; np++) {
            uint32_t rh[4], rl[4];
            uint32_t bd = sbuf + AS_KH + swz(nwb + np * 16 + brow, bseg);
            ldmx4(rh, bd);
            ldmx4(rl, bd + (AS_KL - AS_KH));
#pragma unroll
            for (int mf = 0; mf < 4; mf++) {
                mma16816h(acc[mf][2*np],   ah[mf], rh);
                mma16816h(acc[mf][2*np+1], ah[mf], rh + 2);
                mma16816h(acc[mf][2*np],   ah[mf], rl);
                mma16816h(acc[mf][2*np+1], ah[mf], rl + 2);
            }
        }
    }

    // Prefetch first V tiles (region does not overlap scores stages)
    const __half* pVh = V16h + (size_t)z * HD_DIM * T_DIM;
    const __half* pVl = V16l + (size_t)z * HD_DIM * T_DIM;
    const size_t vsrc = (size_t)crow * T_DIM + cseg * 8;
    const uint32_t vdst = swz(crow, cseg);
    auto issueV = [&](int c) {
        const uint32_t st = sbase + AS_VOFF + (c % 3) * 8192;
        cp16(st + vdst,        pVh + vsrc + c * 16);
        cp16(st + vdst + 4096, pVl + vsrc + c * 16);
    };
    issueV(0); CP_COMMIT();
    issueV(1); CP_COMMIT();
    __syncthreads();   // all warps done with scores stages before P overwrite

    // ---- mask/scale/clip + per-row softmax ----
    const float invs = 0.08838834764831845f;   // 1/sqrt(128)
    float rmax[4][2], rsum[4][2];
#pragma unroll
    for (int mf = 0; mf < 4; mf++) {
        float mx0 = -1e30f, mx1 = -1e30f;
#pragma unroll
        for (int nf = 0; nf < 8; nf++) {
            const int col = nwb + nf * 8 + ti * 2;
            const bool k0 = smask[col] != 0;
            const bool k1 = smask[col + 1] != 0;
            float* a = acc[mf][nf];
            a[0] = k0 ? fminf(fmaxf(a[0] * invs, -50.f), 50.f) : -50.f;
            a[1] = k1 ? fminf(fmaxf(a[1] * invs, -50.f), 50.f) : -50.f;
            a[2] = k0 ? fminf(fmaxf(a[2] * invs, -50.f), 50.f) : -50.f;
            a[3] = k1 ? fminf(fmaxf(a[3] * invs, -50.f), 50.f) : -50.f;
            mx0 = fmaxf(mx0, fmaxf(a[0], a[1]));
            mx1 = fmaxf(mx1, fmaxf(a[2], a[3]));
        }
        mx0 = fmaxf(mx0, __shfl_xor_sync(0xffffffffu, mx0, 1));
        mx0 = fmaxf(mx0, __shfl_xor_sync(0xffffffffu, mx0, 2));
        mx1 = fmaxf(mx1, __shfl_xor_sync(0xffffffffu, mx1, 1));
        mx1 = fmaxf(mx1, __shfl_xor_sync(0xffffffffu, mx1, 2));
        if (ti == 0) {
            red[mwb + mf * 16 + g][wid & 3]     = mx0;
            red[mwb + mf * 16 + g + 8][wid & 3] = mx1;
        }
    }
    __syncthreads();
#pragma unroll
    for (int mf = 0; mf < 4; mf++) {
        float4 r0 = *(float4*)red[mwb + mf * 16 + g];
        rmax[mf][0] = fmaxf(fmaxf(r0.x, r0.y), fmaxf(r0.z, r0.w));
        float4 r1 = *(float4*)red[mwb + mf * 16 + g + 8];
        rmax[mf][1] = fmaxf(fmaxf(r1.x, r1.y), fmaxf(r1.z, r1.w));
    }
    __syncthreads();
#pragma unroll
    for (int mf = 0; mf < 4; mf++) {
        float s0 = 0.f, s1 = 0.f;
#pragma unroll
        for (int nf = 0; nf < 8; nf++) {
            float* a = acc[mf][nf];
            a[0] = __expf(a[0] - rmax[mf][0]); s0 += a[0];
            a[1] = __expf(a[1] - rmax[mf][0]); s0 += a[1];
            a[2] = __expf(a[2] - rmax[mf][1]); s1 += a[2];
            a[3] = __expf(a[3] - rmax[mf][1]); s1 += a[3];
        }
        s0 += __shfl_xor_sync(0xffffffffu, s0, 1);
        s0 += __shfl_xor_sync(0xffffffffu, s0, 2);
        s1 += __shfl_xor_sync(0xffffffffu, s1, 1);
        s1 += __shfl_xor_sync(0xffffffffu, s1, 2);
        if (ti == 0) {
            red[mwb + mf * 16 + g][wid & 3]     = s0;
            red[mwb + mf * 16 + g + 8][wid & 3] = s1;
        }
    }
    __syncthreads();
#pragma unroll
    for (int mf = 0; mf < 4; mf++) {
        float4 r0 = *(float4*)red[mwb + mf * 16 + g];
        rsum[mf][0] = 1.f / (r0.x + r0.y + r0.z + r0.w);
        float4 r1 = *(float4*)red[mwb + mf * 16 + g + 8];
        rsum[mf][1] = 1.f / (r1.x + r1.y + r1.z + r1.w);
    }

    // ---- stage P (single fp16) into SMEM A-operand tiles: chunk ch at ch*4096 ----
#pragma unroll
    for (int mf = 0; mf < 4; mf++) {
        const int r0 = mwb + mf * 16 + g;
#pragma unroll
        for (int nf = 0; nf < 8; nf++) {
            const int col = nwb + nf * 8 + ti * 2;
            const int ch = col >> 4;
            const int colc = col & 15;
            const uint32_t cb = ch * 4096 + (((colc >> 3) << 4) ^ ((r0 & 4) << 2))
                              + (colc & 7) * 2 + r0 * 32;
            float* a = acc[mf][nf];
            *(uint32_t*)(dsm + cb)       = pack_h2(a[0] * rsum[mf][0], a[1] * rsum[mf][0]);
            *(uint32_t*)(dsm + cb + 256) = pack_h2(a[2] * rsum[mf][1], a[3] * rsum[mf][1]);
        }
    }
    __syncthreads();

    // ---- PV mainloop: ctx[128 s][128 d], K = T = 256, 16 chunks ----
    float ctx[4][4][4];
#pragma unroll
    for (int i = 0; i < 4; i++)
#pragma unroll
        for (int j = 0; j < 4; j++)
#pragma unroll
            for (int q = 0; q < 4; q++) ctx[i][j][q] = 0.f;

    const int nwb2 = (wid & 3) * 32;
    for (int c = 0; c < 16; c++) {
        CP_WAIT1();
        __syncthreads();
        if (c + 2 < 16) issueV(c + 2);
        CP_COMMIT();

        const uint32_t pbuf = sbase + c * 4096;
        const uint32_t vbuf = sbase + AS_VOFF + (c % 3) * 8192;
        uint32_t ah[4][4];
#pragma unroll
        for (int mf = 0; mf < 4; mf++)
            ldmx4(ah[mf], pbuf + swz(mwb + mf * 16 + arow, aseg));
#pragma unroll
        for (int np = 0; np < 2; np++) {
            uint32_t rh[4], rl[4];
            uint32_t bd = vbuf + swz(nwb2 + np * 16 + brow, bseg);
            ldmx4(rh, bd);
            ldmx4(rl, bd + 4096);
#pragma unroll
            for (int mf = 0; mf < 4; mf++) {
                mma16816h(ctx[mf][2*np],   ah[mf], rh);
                mma16816h(ctx[mf][2*np+1], ah[mf], rh + 2);
                mma16816h(ctx[mf][2*np],   ah[mf], rl);
                mma16816h(ctx[mf][2*np+1], ah[mf], rl + 2);
            }
        }
    }
    __syncthreads();

    // ---- ctx scatter -> single fp16 [b*S+s, h*128+d] ----
    float* stage = (float*)dsm;
#pragma unroll
    for (int p = 0; p < 2; p++) {
        if (p) __syncthreads();
#pragma unroll
        for (int mf = 0; mf < 4; mf++)
#pragma unroll
            for (int e = 0; e < 2; e++) {
                const int nf = 2 * p + e;
                const int row = mwb + mf * 16 + g;
                const int cm = (wid & 3) * 16 + e * 8 + ti * 2;
                *(float2*)&stage[row * STAGE_PITCH + cm] =
                    make_float2(ctx[mf][nf][0], ctx[mf][nf][1]);
                *(float2*)&stage[(row + 8) * STAGE_PITCH + cm] =
                    make_float2(ctx[mf][nf][2], ctx[mf][nf][3]);
            }
        __syncthreads();
#pragma unroll
        for (int it = 0; it < 8; it++) {
            const int lin = it * 1024 + tid * 4;
            const int row = lin >> 6;
            const int cm = lin & 63;
            const int col = ((cm >> 4) << 5) + (p << 4) + (cm & 15);
            float4 v = *(float4*)&stage[row * STAGE_PITCH + cm];
            size_t off = (size_t)(bb * S_DIM + m0 + row) * H_DIM + hh * HD_DIM + col;
            *(uint2*)(C16 + off) = make_uint2(pack_h2(v.x, v.y), pack_h2(v.z, v.w));
        }
    }
}

// ---------------------------------------------------------------------------
// LayerNorm
// ---------------------------------------------------------------------------
__device__ __forceinline__ float block_sum(float v)
{
    __shared__ float red[8];
#pragma unroll
    for (int o = 16; o; o >>= 1) v += __shfl_xor_sync(0xffffffffu, v, o);
    int w = threadIdx.x >> 5;
    if ((threadIdx.x & 31) == 0) red[w] = v;
    __syncthreads();
    float t = (threadIdx.x < 8) ? red[threadIdx.x] : 0.f;
    if (threadIdx.x < 32) {
#pragma unroll
        for (int o = 4; o; o >>= 1) t += __shfl_xor_sync(0xffffffffu, t, o);
        if (threadIdx.x == 0) red[0] = t;
    }
    __syncthreads();
    float r = red[0];
    __syncthreads();
    return r;
}

__global__ void ln_kernel(const float* __restrict__ D, const float* __restrict__ gamma,
                          const float* __restrict__ beta, const float* __restrict__ rsp,
                          float* __restrict__ out)
{
    int row = blockIdx.x;
    int tid = threadIdx.x;
    float rs = fminf(fmaxf(rsp[0], 0.f), 0.3f);

    const float* d = D + (size_t)row * H_DIM;
    float4 u0 = *(const float4*)(d + tid * 4);
    float4 u1 = *(const float4*)(d + 1024 + tid * 4);
    float x[8] = {rs*u0.x, rs*u0.y, rs*u0.z, rs*u0.w,
                  rs*u1.x, rs*u1.y, rs*u1.z, rs*u1.w};

    float ps = 0.f;
#pragma unroll
    for (int i = 0; i < 8; i++) ps += x[i];
    float mean = block_sum(ps) * (1.f / 2048.f);

    float pv = 0.f;
#pragma unroll
    for (int i = 0; i < 8; i++) { float dd = x[i] - mean; pv += dd * dd; }
    float var = block_sum(pv) * (1.f / 2048.f);
    float inv = rsqrtf(var + 1e-5f);

    float4 gz0 = *(const float4*)(gamma + tid * 4);
    float4 gz1 = *(const float4*)(gamma + 1024 + tid * 4);
    float4 bz0 = *(const float4*)(beta + tid * 4);
    float4 bz1 = *(const float4*)(beta + 1024 + tid * 4);

    float* o = out + (size_t)row * H_DIM;
    *(float4*)(o + tid * 4) = make_float4(
        (x[0]-mean)*inv*gz0.x + bz0.x, (x[1]-mean)*inv*gz0.y + bz0.y,
        (x[2]-mean)*inv*gz0.z + bz0.z, (x[3]-mean)*inv*gz0.w + bz0.w);
    *(float4*)(o + 1024 + tid * 4) = make_float4(
        (x[4]-mean)*inv*gz1.x + bz1.x, (x[5]-mean)*inv*gz1.y + bz1.y,
        (x[6]-mean)*inv*gz1.z + bz1.z, (x[7]-mean)*inv*gz1.w + bz1.w);
}

// ---------------------------------------------------------------------------
// Launch
// ---------------------------------------------------------------------------
extern "C" void kernel_launch(void* const* d_in, const int* in_sizes, int n_in,
                              void* d_out, int out_size)
{
    const float* hs    = (const float*)d_in[0];
    const float* at    = (const float*)d_in[1];
    const int*   mask  = (const int*)  d_in[2];
    const float* Wq    = (const float*)d_in[3];
    const float* bq    = (const float*)d_in[4];
    const float* Wk    = (const float*)d_in[5];
    const float* bk    = (const float*)d_in[6];
    const float* Wv    = (const float*)d_in[7];
    const float* bv    = (const float*)d_in[8];
    const float* Wo    = (const float*)d_in[9];
    const float* bo    = (const float*)d_in[10];
    const float* gamma = (const float*)d_in[11];
    const float* beta  = (const float*)d_in[12];
    const float* rsp   = (const float*)d_in[13];
    float* out = (float*)d_out;

    __half *hs16, *at16h, *at16l, *Wq16h, *Wq16l, *Wk16h, *Wk16l, *Wv16, *Wo16h, *Wo16l;
    __half *Q16, *K16h, *K16l, *Vt16h, *Vt16l, *C16;
    float *Db;
    cudaGetSymbolAddress((void**)&hs16,  g_hs16);
    cudaGetSymbolAddress((void**)&at16h, g_at16h); cudaGetSymbolAddress((void**)&at16l, g_at16l);
    cudaGetSymbolAddress((void**)&Wq16h, g_Wq16h); cudaGetSymbolAddress((void**)&Wq16l, g_Wq16l);
    cudaGetSymbolAddress((void**)&Wk16h, g_Wk16h); cudaGetSymbolAddress((void**)&Wk16l, g_Wk16l);
    cudaGetSymbolAddress((void**)&Wv16,  g_Wv16);
    cudaGetSymbolAddress((void**)&Wo16h, g_Wo16h); cudaGetSymbolAddress((void**)&Wo16l, g_Wo16l);
    cudaGetSymbolAddress((void**)&Q16,   g_Q16);
    cudaGetSymbolAddress((void**)&K16h,  g_K16h);  cudaGetSymbolAddress((void**)&K16l,  g_K16l);
    cudaGetSymbolAddress((void**)&Vt16h, g_Vt16h); cudaGetSymbolAddress((void**)&Vt16l, g_Vt16l);
    cudaGetSymbolAddress((void**)&C16,   g_C16);
    cudaGetSymbolAddress((void**)&Db,    g_D);

    cudaFuncSetAttribute(fused_attn_kernel,
                         cudaFuncAttributeMaxDynamicSharedMemorySize, AS_SMEM);

    // Pre-pass (4 launches)
    cast16_kernel<<<16384, 256>>>(hs, hs16);
    cast16_kernel<<<4096, 256>>>(Wv, Wv16);
    split16_kernel<<<2048, 256>>>(at, at16h, at16l);
    split16x3_kernel<<<dim3(4096, 3), 256>>>(Wq, Wq16h, Wq16l,
                                             Wk, Wk16h, Wk16l,
                                             Wo, Wo16h, Wo16l);

    // Q projection -> fp16 single
    mma_gemm_f16<0><<<dim3(16, 64), 256>>>(hs16, Wq16h, Wq16l, bq,
                                           nullptr, Q16, 2048, 2048, 2048, 2048);
    // K-proj + V-proj in one launch (concurrent chip fill)
    mma_gemm_kv<<<dim3(16, 16, 2), 256>>>(at16h, at16l, Wk16h, Wk16l, Wv16,
                                          bk, bv, K16h, K16l, Vt16h, Vt16l);
    // Fused scores + softmax + PV -> ctx fp16
    fused_attn_kernel<<<dim3(1, 16, 64), 256, AS_SMEM>>>(Q16, K16h, K16l,
                                                         Vt16h, Vt16l, mask, C16);
    // O projection -> fp32
    mma_gemm_f16<4><<<dim3(16, 64), 256>>>(C16, Wo16h, Wo16l, bo,
                                           Db, nullptr, 2048, 2048, 2048, 2048);
    // residual scale + LayerNorm
    ln_kernel<<<8192, 256>>>(Db, gamma, beta, rsp, out);
}

// round 17
// speedup vs baseline: 1.0836x; 1.0217x over previous
#include <cuda_runtime.h>
#include <cuda_fp16.h>
#include <cstdint>
#include <math.h>

#define B_DIM 4
#define S_DIM 2048
#define T_DIM 256
#define H_DIM 2048
#define NHEAD 16
#define HD_DIM 128

#define BK 16
#define STAGE_PITCH 68       // fp32 epilogue staging pitch

// fp16 2-term GEMM: 128x128 tile, BK=16, 4-stage ring (12KB/stage), 2 CTAs/SM
#define FT 4096
#define FSTG 12288
#define SMEM_BYTES 49152

// Fused attention (128 q-rows, occ 1 — proven optimum)
#define AS_KH 4096
#define AS_KL 12288
#define AS_STG 24576
#define AS_VOFF 131072
#define AS_SMEM (AS_VOFF + 3*8192)   // 155648

// ---------------------------------------------------------------------------
// Persistent scratch
// ---------------------------------------------------------------------------
__device__ __half g_hs16[8192*2048];
__device__ __half g_at16h[1024*2048], g_at16l[1024*2048];
__device__ __half g_Wq16h[2048*2048], g_Wq16l[2048*2048];
__device__ __half g_Wk16h[2048*2048], g_Wk16l[2048*2048];
__device__ __half g_Wv16[2048*2048];
__device__ __half g_Wo16h[2048*2048], g_Wo16l[2048*2048];
__device__ __half g_Q16[8192*2048];
__device__ __half g_K16h[1024*2048], g_K16l[1024*2048];
__device__ __half g_Vt16h[64*128*256], g_Vt16l[64*128*256];
__device__ __half g_C16[8192*2048];
__device__ __half g_D16[8192*2048];

// ---------------------------------------------------------------------------
// Helpers
// ---------------------------------------------------------------------------
__device__ __forceinline__ uint32_t smem_to_u32(const void* p) {
    uint32_t a;
    asm("{ .reg .u64 t; cvta.to.shared.u64 t, %1; cvt.u32.u64 %0, t; }" : "=r"(a) : "l"(p));
    return a;
}
__device__ __forceinline__ void cp16(uint32_t dst, const void* src) {
    asm volatile("cp.async.cg.shared.global [%0], [%1], 16;" :: "r"(dst), "l"(src));
}
#define CP_COMMIT() asm volatile("cp.async.commit_group;")
#define CP_WAIT1()  asm volatile("cp.async.wait_group 1;")
#define CP_WAIT2()  asm volatile("cp.async.wait_group 2;")

__device__ __forceinline__ void ldmx4(uint32_t* r, uint32_t addr) {
    asm volatile("ldmatrix.sync.aligned.m8n8.x4.shared.b16 {%0,%1,%2,%3}, [%4];"
                 : "=r"(r[0]), "=r"(r[1]), "=r"(r[2]), "=r"(r[3]) : "r"(addr));
}
__device__ __forceinline__ void mma16816h(float* c, const uint32_t* a, const uint32_t* b) {
    asm volatile("mma.sync.aligned.m16n8k16.row.col.f32.f16.f16.f32 "
                 "{%0,%1,%2,%3}, {%4,%5,%6,%7}, {%8,%9}, {%0,%1,%2,%3};"
                 : "+f"(c[0]), "+f"(c[1]), "+f"(c[2]), "+f"(c[3])
                 : "r"(a[0]), "r"(a[1]), "r"(a[2]), "r"(a[3]), "r"(b[0]), "r"(b[1]));
}
__device__ __forceinline__ void split_pair_f16(float x0, float x1, uint32_t& hi, uint32_t& lo) {
    __half2 h = __floats2half2_rn(x0, x1);
    float r0 = x0 - __half2float(__low2half(h));
    float r1 = x1 - __half2float(__high2half(h));
    __half2 l = __floats2half2_rn(r0, r1);
    hi = *(uint32_t*)&h;
    lo = *(uint32_t*)&l;
}
__device__ __forceinline__ uint32_t pack_h2(float x0, float x1) {
    __half2 h = __floats2half2_rn(x0, x1);
    return *(uint32_t*)&h;
}
__device__ __forceinline__ uint32_t swz(int row, int seg) {
    return (row >> 7) * 4096 + (row & 127) * 32 + ((seg << 4) ^ ((row & 4) << 2));
}

// ---------------------------------------------------------------------------
// Unified pre-pass: one launch, 1-D grid, range-decoded tasks.
//  [0,16384)        cast hs        (8192*2048 fp32 -> fp16)
//  [16384,20480)    cast Wv
//  [20480,22528)    split at
//  [22528,26624)    split Wq
//  [26624,30720)    split Wk
//  [30720,34816)    split Wo
// ---------------------------------------------------------------------------
#define PREPASS_BLOCKS 34816
__global__ void prepass_kernel(const float* __restrict__ hs, __half* __restrict__ hs16,
                               const float* __restrict__ Wv, __half* __restrict__ Wv16,
                               const float* __restrict__ at, __half* __restrict__ ath, __half* __restrict__ atl,
                               const float* __restrict__ Wq, __half* __restrict__ Wqh, __half* __restrict__ Wql,
                               const float* __restrict__ Wk, __half* __restrict__ Wkh, __half* __restrict__ Wkl,
                               const float* __restrict__ Wo, __half* __restrict__ Woh, __half* __restrict__ Wol)
{
    const int b = blockIdx.x;
    if (b < 20480) {   // cast tasks
        const float* in;
        __half* out;
        int base;
        if (b < 16384) { in = hs; out = hs16; base = b; }
        else           { in = Wv; out = Wv16; base = b - 16384; }
        int idx = base * 256 + threadIdx.x;
        float4 v = ((const float4*)in)[idx];
        ((uint2*)out)[idx] = make_uint2(pack_h2(v.x, v.y), pack_h2(v.z, v.w));
    } else {           // split tasks
        const float* in;
        __half *hi, *lo;
        int base;
        if (b < 22528)      { in = at; hi = ath; lo = atl; base = b - 20480; }
        else if (b < 26624) { in = Wq; hi = Wqh; lo = Wql; base = b - 22528; }
        else if (b < 30720) { in = Wk; hi = Wkh; lo = Wkl; base = b - 26624; }
        else                { in = Wo; hi = Woh; lo = Wol; base = b - 30720; }
        int idx = base * 256 + threadIdx.x;
        float4 v = ((const float4*)in)[idx];
        uint32_t h0, l0, h1, l1;
        split_pair_f16(v.x, v.y, h0, l0);
        split_pair_f16(v.z, v.w, h1, l1);
        ((uint2*)hi)[idx] = make_uint2(h0, h1);
        ((uint2*)lo)[idx] = make_uint2(l0, l1);
    }
}

// ---------------------------------------------------------------------------
// fp16 2-term GEMM (frozen mainloop): C = Ah*(Bh+Bl) + bias[col] -> fp16.
// Used for Q-proj (out=Q16) and O-proj (out=D16). 4-stage ring, 2 CTAs/SM.
// ---------------------------------------------------------------------------
__global__ void __launch_bounds__(256, 2)
mma_gemm_f16(const __half* __restrict__ Ah, const __half* __restrict__ Bh,
             const __half* __restrict__ Bl, const float* __restrict__ bias,
             __half* __restrict__ C1, int K, int lda, int ldb, int ldc)
{
    __shared__ __align__(16) char smem[SMEM_BYTES];
    const int tid = threadIdx.x;
    const int wid = tid >> 5;
    const int lane = tid & 31;
    const int g = lane >> 2, ti = lane & 3;
    const int mwb = (wid >> 2) * 64;
    const int nwb = (wid & 3) * 32;
    const uint32_t sbase = smem_to_u32(smem);

    const int m0 = blockIdx.y * 128;
    const int n0 = blockIdx.x * 128;

    const int crow = tid >> 1;
    const int cseg = tid & 1;
    const size_t asrc = (size_t)(m0 + crow) * lda + cseg * 8;
    const size_t bsrc = (size_t)(n0 + crow) * ldb + cseg * 8;
    const uint32_t cdst = swz(crow, cseg);

    const int nchunk = K / BK;

    auto issue = [&](int c) {
        const uint32_t st = sbase + (c & 3) * FSTG;
        const int kt = c * BK;
        cp16(st + cdst,          Ah + asrc + kt);
        cp16(st + cdst + FT,     Bh + bsrc + kt);
        cp16(st + cdst + 2*FT,   Bl + bsrc + kt);
    };

    float acc[4][4][4];
#pragma unroll
    for (int i = 0; i < 4; i++)
#pragma unroll
        for (int j = 0; j < 4; j++)
#pragma unroll
            for (int q = 0; q < 4; q++) acc[i][j][q] = 0.f;

    issue(0); CP_COMMIT();
    issue(1); CP_COMMIT();
    issue(2); CP_COMMIT();

    const int arow = lane & 15;
    const int aseg = lane >> 4;
    const int brow = (lane & 7) + ((lane >> 4) << 3);
    const int bseg = (lane >> 3) & 1;

    for (int c = 0; c < nchunk; c++) {
        CP_WAIT2();
        __syncthreads();
        if (c + 3 < nchunk) issue(c + 3);
        CP_COMMIT();

        const uint32_t sbuf = sbase + (c & 3) * FSTG;
        uint32_t ah[4][4];
#pragma unroll
        for (int mf = 0; mf < 4; mf++)
            ldmx4(ah[mf], sbuf + swz(mwb + mf * 16 + arow, aseg));
#pragma unroll
        for (int np = 0; np < 2; np++) {
            uint32_t rh[4], rl[4];
            uint32_t bd = sbuf + FT + swz(nwb + np * 16 + brow, bseg);
            ldmx4(rh, bd);
            ldmx4(rl, bd + FT);
#pragma unroll
            for (int mf = 0; mf < 4; mf++) {
                mma16816h(acc[mf][2*np],   ah[mf], rh);
                mma16816h(acc[mf][2*np+1], ah[mf], rh + 2);
                mma16816h(acc[mf][2*np],   ah[mf], rl);
                mma16816h(acc[mf][2*np+1], ah[mf], rl + 2);
            }
        }
    }
    __syncthreads();

    float* stage = (float*)smem;
#pragma unroll
    for (int p = 0; p < 2; p++) {
        if (p) __syncthreads();
#pragma unroll
        for (int mf = 0; mf < 4; mf++)
#pragma unroll
            for (int e = 0; e < 2; e++) {
                const int nf = 2 * p + e;
                const int row = mwb + mf * 16 + g;
                const int cm = (wid & 3) * 16 + e * 8 + ti * 2;
                *(float2*)&stage[row * STAGE_PITCH + cm] =
                    make_float2(acc[mf][nf][0], acc[mf][nf][1]);
                *(float2*)&stage[(row + 8) * STAGE_PITCH + cm] =
                    make_float2(acc[mf][nf][2], acc[mf][nf][3]);
            }
        __syncthreads();
#pragma unroll
        for (int it = 0; it < 8; it++) {
            const int lin = it * 1024 + tid * 4;
            const int row = lin >> 6;
            const int cm = lin & 63;
            const int col = ((cm >> 4) << 5) + (p << 4) + (cm & 15);
            float4 v = *(float4*)&stage[row * STAGE_PITCH + cm];
            float4 b4 = *(const float4*)(bias + n0 + col);
            size_t off = (size_t)(m0 + row) * ldc + n0 + col;
            *(uint2*)(C1 + off) = make_uint2(pack_h2(v.x + b4.x, v.y + b4.y),
                                             pack_h2(v.z + b4.z, v.w + b4.w));
        }
    }
}

// ---------------------------------------------------------------------------
// Combined K-proj + V-proj (frozen mainloop), one launch (z selects mode).
// ---------------------------------------------------------------------------
__global__ void __launch_bounds__(256, 2)
mma_gemm_kv(const __half* __restrict__ at16h, const __half* __restrict__ at16l,
            const __half* __restrict__ Wk16h, const __half* __restrict__ Wk16l,
            const __half* __restrict__ Wv16,
            const float* __restrict__ bk, const float* __restrict__ bv,
            __half* __restrict__ K16h, __half* __restrict__ K16l,
            __half* __restrict__ Vth, __half* __restrict__ Vtl)
{
    __shared__ __align__(16) char smem[SMEM_BYTES];
    const int kv = blockIdx.z;    // 0 = K-proj, 1 = V-proj
    if ((kv == 0 && blockIdx.y >= 8) || (kv == 1 && blockIdx.x >= 8)) return;

    const __half* Ah = kv ? Wv16  : at16h;
    const __half* Bh = kv ? at16h : Wk16h;
    const __half* Bl = kv ? at16l : Wk16l;
    const float* bias = kv ? bv : bk;

    const int tid = threadIdx.x;
    const int wid = tid >> 5;
    const int lane = tid & 31;
    const int g = lane >> 2, ti = lane & 3;
    const int mwb = (wid >> 2) * 64;
    const int nwb = (wid & 3) * 32;
    const uint32_t sbase = smem_to_u32(smem);

    const int m0 = blockIdx.y * 128;
    const int n0 = blockIdx.x * 128;

    const int crow = tid >> 1;
    const int cseg = tid & 1;
    const size_t asrc = (size_t)(m0 + crow) * H_DIM + cseg * 8;
    const size_t bsrc = (size_t)(n0 + crow) * H_DIM + cseg * 8;
    const uint32_t cdst = swz(crow, cseg);

    const int nchunk = H_DIM / BK;   // 128

    auto issue = [&](int c) {
        const uint32_t st = sbase + (c & 3) * FSTG;
        const int kt = c * BK;
        cp16(st + cdst,          Ah + asrc + kt);
        cp16(st + cdst + FT,     Bh + bsrc + kt);
        cp16(st + cdst + 2*FT,   Bl + bsrc + kt);
    };

    float acc[4][4][4];
#pragma unroll
    for (int i = 0; i < 4; i++)
#pragma unroll
        for (int j = 0; j < 4; j++)
#pragma unroll
            for (int q = 0; q < 4; q++) acc[i][j][q] = 0.f;

    issue(0); CP_COMMIT();
    issue(1); CP_COMMIT();
    issue(2); CP_COMMIT();

    const int arow = lane & 15;
    const int aseg = lane >> 4;
    const int brow = (lane & 7) + ((lane >> 4) << 3);
    const int bseg = (lane >> 3) & 1;

    for (int c = 0; c < nchunk; c++) {
        CP_WAIT2();
        __syncthreads();
        if (c + 3 < nchunk) issue(c + 3);
        CP_COMMIT();

        const uint32_t sbuf = sbase + (c & 3) * FSTG;
        uint32_t ah[4][4];
#pragma unroll
        for (int mf = 0; mf < 4; mf++)
            ldmx4(ah[mf], sbuf + swz(mwb + mf * 16 + arow, aseg));
#pragma unroll
        for (int np = 0; np < 2; np++) {
            uint32_t rh[4], rl[4];
            uint32_t bd = sbuf + FT + swz(nwb + np * 16 + brow, bseg);
            ldmx4(rh, bd);
            ldmx4(rl, bd + FT);
#pragma unroll
            for (int mf = 0; mf < 4; mf++) {
                mma16816h(acc[mf][2*np],   ah[mf], rh);
                mma16816h(acc[mf][2*np+1], ah[mf], rh + 2);
                mma16816h(acc[mf][2*np],   ah[mf], rl);
                mma16816h(acc[mf][2*np+1], ah[mf], rl + 2);
            }
        }
    }
    __syncthreads();

    float* stage = (float*)smem;
#pragma unroll
    for (int p = 0; p < 2; p++) {
        if (p) __syncthreads();
#pragma unroll
        for (int mf = 0; mf < 4; mf++)
#pragma unroll
            for (int e = 0; e < 2; e++) {
                const int nf = 2 * p + e;
                const int row = mwb + mf * 16 + g;
                const int cm = (wid & 3) * 16 + e * 8 + ti * 2;
                *(float2*)&stage[row * STAGE_PITCH + cm] =
                    make_float2(acc[mf][nf][0], acc[mf][nf][1]);
                *(float2*)&stage[(row + 8) * STAGE_PITCH + cm] =
                    make_float2(acc[mf][nf][2], acc[mf][nf][3]);
            }
        __syncthreads();
#pragma unroll
        for (int it = 0; it < 8; it++) {
            const int lin = it * 1024 + tid * 4;
            const int row = lin >> 6;
            const int cm = lin & 63;
            const int col = ((cm >> 4) << 5) + (p << 4) + (cm & 15);
            float4 v = *(float4*)&stage[row * STAGE_PITCH + cm];
            if (kv == 0) {          // K-proj epilogue (bias per col, hi/lo pair)
                float4 b4 = *(const float4*)(bias + n0 + col);
                size_t off = (size_t)(m0 + row) * H_DIM + n0 + col;
                uint32_t h0, l0, h1, l1;
                split_pair_f16(v.x + b4.x, v.y + b4.y, h0, l0);
                split_pair_f16(v.z + b4.z, v.w + b4.w, h1, l1);
                *(uint2*)(K16h + off) = make_uint2(h0, h1);
                *(uint2*)(K16l + off) = make_uint2(l0, l1);
            } else {                // V-proj scatter (bias per row)
                const int gr = m0 + row;             // feature = h*128+d
                const int h = gr >> 7, d = gr & 127;
                const int n = n0 + col;              // b*256+t
                const int b = n >> 8, t = n & 255;
                const float br = bias[gr];
                size_t off = ((size_t)(b * NHEAD + h) * HD_DIM + d) * T_DIM + t;
                uint32_t h0, l0, h1, l1;
                split_pair_f16(v.x + br, v.y + br, h0, l0);
                split_pair_f16(v.z + br, v.w + br, h1, l1);
                *(uint2*)(Vth + off) = make_uint2(h0, h1);
                *(uint2*)(Vtl + off) = make_uint2(l0, l1);
            }
        }
    }
}

// ---------------------------------------------------------------------------
// Fused attention (frozen): 128 q-rows per CTA, occ 1, all fp16 2-term.
// ---------------------------------------------------------------------------
__global__ void __launch_bounds__(256, 1)
fused_attn_kernel(const __half* __restrict__ Q16,
                  const __half* __restrict__ K16h, const __half* __restrict__ K16l,
                  const __half* __restrict__ V16h, const __half* __restrict__ V16l,
                  const int* __restrict__ mask, __half* __restrict__ C16)
{
    extern __shared__ __align__(16) char dsm[];
    __shared__ float red[128][4];
    __shared__ int smask[T_DIM];

    const int tid = threadIdx.x;
    const int wid = tid >> 5;
    const int lane = tid & 31;
    const int g = lane >> 2, ti = lane & 3;
    const int mwb = (wid >> 2) * 64;
    const int nwb = (wid & 3) * 64;
    const uint32_t sbase = smem_to_u32(dsm);

    const int m0 = blockIdx.y * 128;
    const int z = blockIdx.z;
    const int bb = z >> 4, hh = z & 15;
    const __half* pQ  = Q16  + (size_t)bb * S_DIM * H_DIM + hh * HD_DIM;
    const __half* pKh = K16h + (size_t)bb * T_DIM * H_DIM + hh * HD_DIM;
    const __half* pKl = K16l + (size_t)bb * T_DIM * H_DIM + hh * HD_DIM;

    smask[tid] = mask[bb * T_DIM + tid];

    const int crow = tid >> 1, cseg = tid & 1;
    const size_t qsrc  = (size_t)(m0 + crow) * H_DIM + cseg * 8;
    const size_t ksrc0 = (size_t)crow * H_DIM + cseg * 8;
    const size_t ksrc1 = (size_t)(crow + 128) * H_DIM + cseg * 8;
    const uint32_t adst = swz(crow, cseg);
    const uint32_t bdst0 = swz(crow, cseg);
    const uint32_t bdst1 = swz(crow + 128, cseg);

    auto issue = [&](int c) {
        const uint32_t st = sbase + (c % 3) * AS_STG;
        const int kt = c * BK;
        cp16(st + adst,            pQ  + qsrc + kt);
        cp16(st + AS_KH + bdst0,   pKh + ksrc0 + kt);
        cp16(st + AS_KH + bdst1,   pKh + ksrc1 + kt);
        cp16(st + AS_KL + bdst0,   pKl + ksrc0 + kt);
        cp16(st + AS_KL + bdst1,   pKl + ksrc1 + kt);
    };

    float acc[4][8][4];
#pragma unroll
    for (int i = 0; i < 4; i++)
#pragma unroll
        for (int j = 0; j < 8; j++)
#pragma unroll
            for (int q = 0; q < 4; q++) acc[i][j][q] = 0.f;

    issue(0); CP_COMMIT();
    issue(1); CP_COMMIT();

    const int arow = lane & 15;
    const int aseg = lane >> 4;
    const int brow = (lane & 7) + ((lane >> 4) << 3);
    const int bseg = (lane >> 3) & 1;

    for (int c = 0; c < 8; c++) {          // K = HD = 128
        CP_WAIT1();
        __syncthreads();
        if (c + 2 < 8) issue(c + 2);
        CP_COMMIT();

        const uint32_t sbuf = sbase + (c % 3) * AS_STG;
        uint32_t ah[4][4];
#pragma unroll
        for (int mf = 0; mf < 4; mf++)
            ldmx4(ah[mf], sbuf + swz(mwb + mf * 16 + arow, aseg));
#pragma unroll
        for (int np = 0; np < 4; np++) {
            uint32_t rh[4], rl[4];
            uint32_t bd = sbuf + AS_KH + swz(nwb + np * 16 + brow, bseg);
            ldmx4(rh, bd);
            ldmx4(rl, bd + (AS_KL - AS_KH));
#pragma unroll
            for (int mf = 0; mf < 4; mf++) {
                mma16816h(acc[mf][2*np],   ah[mf], rh);
                mma16816h(acc[mf][2*np+1], ah[mf], rh + 2);
                mma16816h(acc[mf][2*np],   ah[mf], rl);
                mma16816h(acc[mf][2*np+1], ah[mf], rl + 2);
            }
        }
    }

    // Prefetch first V tiles
    const __half* pVh = V16h + (size_t)z * HD_DIM * T_DIM;
    const __half* pVl = V16l + (size_t)z * HD_DIM * T_DIM;
    const size_t vsrc = (size_t)crow * T_DIM + cseg * 8;
    const uint32_t vdst = swz(crow, cseg);
    auto issueV = [&](int c) {
        const uint32_t st = sbase + AS_VOFF + (c % 3) * 8192;
        cp16(st + vdst,        pVh + vsrc + c * 16);
        cp16(st + vdst + 4096, pVl + vsrc + c * 16);
    };
    issueV(0); CP_COMMIT();
    issueV(1); CP_COMMIT();
    __syncthreads();

    // ---- mask/scale/clip + per-row softmax ----
    const float invs = 0.08838834764831845f;   // 1/sqrt(128)
    float rmax[4][2], rsum[4][2];
#pragma unroll
    for (int mf = 0; mf < 4; mf++) {
        float mx0 = -1e30f, mx1 = -1e30f;
#pragma unroll
        for (int nf = 0; nf < 8; nf++) {
            const int col = nwb + nf * 8 + ti * 2;
            const bool k0 = smask[col] != 0;
            const bool k1 = smask[col + 1] != 0;
            float* a = acc[mf][nf];
            a[0] = k0 ? fminf(fmaxf(a[0] * invs, -50.f), 50.f) : -50.f;
            a[1] = k1 ? fminf(fmaxf(a[1] * invs, -50.f), 50.f) : -50.f;
            a[2] = k0 ? fminf(fmaxf(a[2] * invs, -50.f), 50.f) : -50.f;
            a[3] = k1 ? fminf(fmaxf(a[3] * invs, -50.f), 50.f) : -50.f;
            mx0 = fmaxf(mx0, fmaxf(a[0], a[1]));
            mx1 = fmaxf(mx1, fmaxf(a[2], a[3]));
        }
        mx0 = fmaxf(mx0, __shfl_xor_sync(0xffffffffu, mx0, 1));
        mx0 = fmaxf(mx0, __shfl_xor_sync(0xffffffffu, mx0, 2));
        mx1 = fmaxf(mx1, __shfl_xor_sync(0xffffffffu, mx1, 1));
        mx1 = fmaxf(mx1, __shfl_xor_sync(0xffffffffu, mx1, 2));
        if (ti == 0) {
            red[mwb + mf * 16 + g][wid & 3]     = mx0;
            red[mwb + mf * 16 + g + 8][wid & 3] = mx1;
        }
    }
    __syncthreads();
#pragma unroll
    for (int mf = 0; mf < 4; mf++) {
        float4 r0 = *(float4*)red[mwb + mf * 16 + g];
        rmax[mf][0] = fmaxf(fmaxf(r0.x, r0.y), fmaxf(r0.z, r0.w));
        float4 r1 = *(float4*)red[mwb + mf * 16 + g + 8];
        rmax[mf][1] = fmaxf(fmaxf(r1.x, r1.y), fmaxf(r1.z, r1.w));
    }
    __syncthreads();
#pragma unroll
    for (int mf = 0; mf < 4; mf++) {
        float s0 = 0.f, s1 = 0.f;
#pragma unroll
        for (int nf = 0; nf < 8; nf++) {
            float* a = acc[mf][nf];
            a[0] = __expf(a[0] - rmax[mf][0]); s0 += a[0];
            a[1] = __expf(a[1] - rmax[mf][0]); s0 += a[1];
            a[2] = __expf(a[2] - rmax[mf][1]); s1 += a[2];
            a[3] = __expf(a[3] - rmax[mf][1]); s1 += a[3];
        }
        s0 += __shfl_xor_sync(0xffffffffu, s0, 1);
        s0 += __shfl_xor_sync(0xffffffffu, s0, 2);
        s1 += __shfl_xor_sync(0xffffffffu, s1, 1);
        s1 += __shfl_xor_sync(0xffffffffu, s1, 2);
        if (ti == 0) {
            red[mwb + mf * 16 + g][wid & 3]     = s0;
            red[mwb + mf * 16 + g + 8][wid & 3] = s1;
        }
    }
    __syncthreads();
#pragma unroll
    for (int mf = 0; mf < 4; mf++) {
        float4 r0 = *(float4*)red[mwb + mf * 16 + g];
        rsum[mf][0] = 1.f / (r0.x + r0.y + r0.z + r0.w);
        float4 r1 = *(float4*)red[mwb + mf * 16 + g + 8];
        rsum[mf][1] = 1.f / (r1.x + r1.y + r1.z + r1.w);
    }

    // ---- stage P (single fp16) into SMEM A-operand tiles ----
#pragma unroll
    for (int mf = 0; mf < 4; mf++) {
        const int r0 = mwb + mf * 16 + g;
#pragma unroll
        for (int nf = 0; nf < 8; nf++) {
            const int col = nwb + nf * 8 + ti * 2;
            const int ch = col >> 4;
            const int colc = col & 15;
            const uint32_t cb = ch * 4096 + (((colc >> 3) << 4) ^ ((r0 & 4) << 2))
                              + (colc & 7) * 2 + r0 * 32;
            float* a = acc[mf][nf];
            *(uint32_t*)(dsm + cb)       = pack_h2(a[0] * rsum[mf][0], a[1] * rsum[mf][0]);
            *(uint32_t*)(dsm + cb + 256) = pack_h2(a[2] * rsum[mf][1], a[3] * rsum[mf][1]);
        }
    }
    __syncthreads();

    // ---- PV mainloop ----
    float ctx[4][4][4];
#pragma unroll
    for (int i = 0; i < 4; i++)
#pragma unroll
        for (int j = 0; j < 4; j++)
#pragma unroll
            for (int q = 0; q < 4; q++) ctx[i][j][q] = 0.f;

    const int nwb2 = (wid & 3) * 32;
    for (int c = 0; c < 16; c++) {
        CP_WAIT1();
        __syncthreads();
        if (c + 2 < 16) issueV(c + 2);
        CP_COMMIT();

        const uint32_t pbuf = sbase + c * 4096;
        const uint32_t vbuf = sbase + AS_VOFF + (c % 3) * 8192;
        uint32_t ah[4][4];
#pragma unroll
        for (int mf = 0; mf < 4; mf++)
            ldmx4(ah[mf], pbuf + swz(mwb + mf * 16 + arow, aseg));
#pragma unroll
        for (int np = 0; np < 2; np++) {
            uint32_t rh[4], rl[4];
            uint32_t bd = vbuf + swz(nwb2 + np * 16 + brow, bseg);
            ldmx4(rh, bd);
            ldmx4(rl, bd + 4096);
#pragma unroll
            for (int mf = 0; mf < 4; mf++) {
                mma16816h(ctx[mf][2*np],   ah[mf], rh);
                mma16816h(ctx[mf][2*np+1], ah[mf], rh + 2);
                mma16816h(ctx[mf][2*np],   ah[mf], rl);
                mma16816h(ctx[mf][2*np+1], ah[mf], rl + 2);
            }
        }
    }
    __syncthreads();

    // ---- ctx scatter -> single fp16 [b*S+s, h*128+d] ----
    float* stage = (float*)dsm;
#pragma unroll
    for (int p = 0; p < 2; p++) {
        if (p) __syncthreads();
#pragma unroll
        for (int mf = 0; mf < 4; mf++)
#pragma unroll
            for (int e = 0; e < 2; e++) {
                const int nf = 2 * p + e;
                const int row = mwb + mf * 16 + g;
                const int cm = (wid & 3) * 16 + e * 8 + ti * 2;
                *(float2*)&stage[row * STAGE_PITCH + cm] =
                    make_float2(ctx[mf][nf][0], ctx[mf][nf][1]);
                *(float2*)&stage[(row + 8) * STAGE_PITCH + cm] =
                    make_float2(ctx[mf][nf][2], ctx[mf][nf][3]);
            }
        __syncthreads();
#pragma unroll
        for (int it = 0; it < 8; it++) {
            const int lin = it * 1024 + tid * 4;
            const int row = lin >> 6;
            const int cm = lin & 63;
            const int col = ((cm >> 4) << 5) + (p << 4) + (cm & 15);
            float4 v = *(float4*)&stage[row * STAGE_PITCH + cm];
            size_t off = (size_t)(bb * S_DIM + m0 + row) * H_DIM + hh * HD_DIM + col;
            *(uint2*)(C16 + off) = make_uint2(pack_h2(v.x, v.y), pack_h2(v.z, v.w));
        }
    }
}

// ---------------------------------------------------------------------------
// LayerNorm (fp16 input D, residual_scale applied), one block per row
// ---------------------------------------------------------------------------
__device__ __forceinline__ float block_sum(float v)
{
    __shared__ float red[8];
#pragma unroll
    for (int o = 16; o; o >>= 1) v += __shfl_xor_sync(0xffffffffu, v, o);
    int w = threadIdx.x >> 5;
    if ((threadIdx.x & 31) == 0) red[w] = v;
    __syncthreads();
    float t = (threadIdx.x < 8) ? red[threadIdx.x] : 0.f;
    if (threadIdx.x < 32) {
#pragma unroll
        for (int o = 4; o; o >>= 1) t += __shfl_xor_sync(0xffffffffu, t, o);
        if (threadIdx.x == 0) red[0] = t;
    }
    __syncthreads();
    float r = red[0];
    __syncthreads();
    return r;
}

__global__ void ln_kernel(const __half* __restrict__ D, const float* __restrict__ gamma,
                          const float* __restrict__ beta, const float* __restrict__ rsp,
                          float* __restrict__ out)
{
    int row = blockIdx.x;
    int tid = threadIdx.x;
    float rs = fminf(fmaxf(rsp[0], 0.f), 0.3f);

    const __half* d = D + (size_t)row * H_DIM;
    uint2 u0 = *(const uint2*)(d + tid * 4);
    uint2 u1 = *(const uint2*)(d + 1024 + tid * 4);
    __half2 p0 = *(__half2*)&u0.x, p1 = *(__half2*)&u0.y;
    __half2 p2 = *(__half2*)&u1.x, p3 = *(__half2*)&u1.y;
    float x[8] = {rs*__half2float(__low2half(p0)), rs*__half2float(__high2half(p0)),
                  rs*__half2float(__low2half(p1)), rs*__half2float(__high2half(p1)),
                  rs*__half2float(__low2half(p2)), rs*__half2float(__high2half(p2)),
                  rs*__half2float(__low2half(p3)), rs*__half2float(__high2half(p3))};

    float ps = 0.f;
#pragma unroll
    for (int i = 0; i < 8; i++) ps += x[i];
    float mean = block_sum(ps) * (1.f / 2048.f);

    float pv = 0.f;
#pragma unroll
    for (int i = 0; i < 8; i++) { float dd = x[i] - mean; pv += dd * dd; }
    float var = block_sum(pv) * (1.f / 2048.f);
    float inv = rsqrtf(var + 1e-5f);

    float4 gz0 = *(const float4*)(gamma + tid * 4);
    float4 gz1 = *(const float4*)(gamma + 1024 + tid * 4);
    float4 bz0 = *(const float4*)(beta + tid * 4);
    float4 bz1 = *(const float4*)(beta + 1024 + tid * 4);

    float* o = out + (size_t)row * H_DIM;
    *(float4*)(o + tid * 4) = make_float4(
        (x[0]-mean)*inv*gz0.x + bz0.x, (x[1]-mean)*inv*gz0.y + bz0.y,
        (x[2]-mean)*inv*gz0.z + bz0.z, (x[3]-mean)*inv*gz0.w + bz0.w);
    *(float4*)(o + 1024 + tid * 4) = make_float4(
        (x[4]-mean)*inv*gz1.x + bz1.x, (x[5]-mean)*inv*gz1.y + bz1.y,
        (x[6]-mean)*inv*gz1.z + bz1.z, (x[7]-mean)*inv*gz1.w + bz1.w);
}

// ---------------------------------------------------------------------------
// Launch
// ---------------------------------------------------------------------------
extern "C" void kernel_launch(void* const* d_in, const int* in_sizes, int n_in,
                              void* d_out, int out_size)
{
    const float* hs    = (const float*)d_in[0];
    const float* at    = (const float*)d_in[1];
    const int*   mask  = (const int*)  d_in[2];
    const float* Wq    = (const float*)d_in[3];
    const float* bq    = (const float*)d_in[4];
    const float* Wk    = (const float*)d_in[5];
    const float* bk    = (const float*)d_in[6];
    const float* Wv    = (const float*)d_in[7];
    const float* bv    = (const float*)d_in[8];
    const float* Wo    = (const float*)d_in[9];
    const float* bo    = (const float*)d_in[10];
    const float* gamma = (const float*)d_in[11];
    const float* beta  = (const float*)d_in[12];
    const float* rsp   = (const float*)d_in[13];
    float* out = (float*)d_out;

    __half *hs16, *at16h, *at16l, *Wq16h, *Wq16l, *Wk16h, *Wk16l, *Wv16, *Wo16h, *Wo16l;
    __half *Q16, *K16h, *K16l, *Vt16h, *Vt16l, *C16, *D16;
    cudaGetSymbolAddress((void**)&hs16,  g_hs16);
    cudaGetSymbolAddress((void**)&at16h, g_at16h); cudaGetSymbolAddress((void**)&at16l, g_at16l);
    cudaGetSymbolAddress((void**)&Wq16h, g_Wq16h); cudaGetSymbolAddress((void**)&Wq16l, g_Wq16l);
    cudaGetSymbolAddress((void**)&Wk16h, g_Wk16h); cudaGetSymbolAddress((void**)&Wk16l, g_Wk16l);
    cudaGetSymbolAddress((void**)&Wv16,  g_Wv16);
    cudaGetSymbolAddress((void**)&Wo16h, g_Wo16h); cudaGetSymbolAddress((void**)&Wo16l, g_Wo16l);
    cudaGetSymbolAddress((void**)&Q16,   g_Q16);
    cudaGetSymbolAddress((void**)&K16h,  g_K16h);  cudaGetSymbolAddress((void**)&K16l,  g_K16l);
    cudaGetSymbolAddress((void**)&Vt16h, g_Vt16h); cudaGetSymbolAddress((void**)&Vt16l, g_Vt16l);
    cudaGetSymbolAddress((void**)&C16,   g_C16);
    cudaGetSymbolAddress((void**)&D16,   g_D16);

    cudaFuncSetAttribute(fused_attn_kernel,
                         cudaFuncAttributeMaxDynamicSharedMemorySize, AS_SMEM);

    // Unified pre-pass (1 launch)
    prepass_kernel<<<PREPASS_BLOCKS, 256>>>(hs, hs16, Wv, Wv16, at, at16h, at16l,
                                            Wq, Wq16h, Wq16l, Wk, Wk16h, Wk16l,
                                            Wo, Wo16h, Wo16l);

    // Q projection -> fp16 single
    mma_gemm_f16<<<dim3(16, 64), 256>>>(hs16, Wq16h, Wq16l, bq,
                                        Q16, 2048, 2048, 2048, 2048);
    // K-proj + V-proj in one launch
    mma_gemm_kv<<<dim3(16, 16, 2), 256>>>(at16h, at16l, Wk16h, Wk16l, Wv16,
                                          bk, bv, K16h, K16l, Vt16h, Vt16l);
    // Fused scores + softmax + PV -> ctx fp16
    fused_attn_kernel<<<dim3(1, 16, 64), 256, AS_SMEM>>>(Q16, K16h, K16l,
                                                         Vt16h, Vt16l, mask, C16);
    // O projection -> fp16 D
    mma_gemm_f16<<<dim3(16, 64), 256>>>(C16, Wo16h, Wo16l, bo,
                                        D16, 2048, 2048, 2048, 2048);
    // residual scale + LayerNorm (fp16 in, fp32 out)
    ln_kernel<<<8192, 256>>>(D16, gamma, beta, rsp, out);
}